// round 10
// baseline (speedup 1.0000x reference)
#include <cuda_runtime.h>
#include <cuda_bf16.h>
#include <math.h>
#include <stdint.h>
#include <stddef.h>

// ---------------- problem constants ----------------
#define NSEQ 8
#define SSEQ 448
#define DMODEL 768
#define MAXT 3584          // >= N*(S-1) = 3576
#define MAXV 50000
#define HTOT 640           // 256 + 128 + 128 + 128 concatenated head dims

// ---------------- device scratch (no allocs allowed) ----------------
__device__ __nv_bfloat16 g_Xb[MAXT * DMODEL];        // gathered predictor states bf16
__device__ __nv_bfloat16 g_Wb[HTOT * DMODEL];        // W^T concat bf16: [n=640][k=768]
__device__ float g_bc[HTOT];                         // concatenated transform biases
__device__ float g_H[MAXT * HTOT];                   // transform output fp32 (post-gelu/LN)
__device__ __nv_bfloat16 g_Hb[MAXT * HTOT];          // bf16 copy of H (post-LN)
__device__ __nv_bfloat16 g_Eb[MAXV * 256];           // bf16 copy of current head's emb
__device__ float g_se[4 * MAXT];                     // per-head per-row sum(exp(z))
__device__ float g_sl[4 * MAXT];                     // per-head per-row sum(z)
__device__ float g_acc[16];                          // loss accumulators

// ---------------- asm helpers ----------------
#define CP_ASYNC16(dst, src) \
    asm volatile("cp.async.cg.shared.global [%0], [%1], 16;\n" :: "r"(dst), "l"(src))
#define CP_COMMIT() asm volatile("cp.async.commit_group;\n" ::)
#define CP_WAIT1()  asm volatile("cp.async.wait_group 1;\n" ::)
#define CP_WAIT2()  asm volatile("cp.async.wait_group 2;\n" ::)

__device__ __forceinline__ void ldsm_x4(uint32_t* r, uint32_t addr) {
    asm volatile("ldmatrix.sync.aligned.m8n8.x4.shared.b16 {%0,%1,%2,%3}, [%4];"
                 : "=r"(r[0]), "=r"(r[1]), "=r"(r[2]), "=r"(r[3]) : "r"(addr));
}

__device__ __forceinline__ void mma_bf16(float* c, const uint32_t* a, const uint32_t* b) {
    asm volatile("mma.sync.aligned.m16n8k16.row.col.f32.bf16.bf16.f32 "
                 "{%0,%1,%2,%3}, {%4,%5,%6,%7}, {%8,%9}, {%0,%1,%2,%3};\n"
                 : "+f"(c[0]), "+f"(c[1]), "+f"(c[2]), "+f"(c[3])
                 : "r"(a[0]), "r"(a[1]), "r"(a[2]), "r"(a[3]), "r"(b[0]), "r"(b[1]));
}

#define BKP 40           // padded smem row stride in bf16 elements (80 bytes)
// ---- transform GEMM staging (128x128) ----
#define STAGE_B (128 * BKP * 2)   // 10240 bytes per operand per stage

// ---- stats GEMM staging (BM=128, BN=256) ----
#define NSTAGE 4
#define ASTG (128 * BKP * 2)      // 10240 B
#define BSTG (256 * BKP * 2)      // 20480 B
#define SMEM_STATS (NSTAGE * (ASTG + BSTG) + 2 * 4 * 128 * 4 + 256 * 4)  // 128000 B

// transform-stage loader: 128 rows x 32 cols of A and B (bf16), 4 cp.async/thread
__device__ __forceinline__ void load_tile_pair(
    const __nv_bfloat16* __restrict__ A, int lda, int Arows, int m0,
    const __nv_bfloat16* __restrict__ B, int ldb, int Brows, int n0,
    int k0, uint32_t a_st, uint32_t b_st, int tid)
{
    #pragma unroll
    for (int i = 0; i < 2; i++) {
        int idx = tid + i * 256;
        int row = idx >> 2, c16 = idx & 3;
        int gm = m0 + row; if (gm >= Arows) gm = Arows - 1;
        CP_ASYNC16(a_st + (row * BKP + c16 * 8) * 2, A + (size_t)gm * lda + k0 + c16 * 8);
        int gn = n0 + row; if (gn >= Brows) gn = Brows - 1;
        CP_ASYNC16(b_st + (row * BKP + c16 * 8) * 2, B + (size_t)gn * ldb + k0 + c16 * 8);
    }
}

// stats-stage loader: A 128x32, B 256x32 (bf16), 6 cp.async/thread
__device__ __forceinline__ void load_tile_128_256(
    const __nv_bfloat16* __restrict__ A, int lda, int Arows, int m0,
    const __nv_bfloat16* __restrict__ B, int ldb, int Brows, int n0,
    int k0, uint32_t a_st, uint32_t b_st, int tid)
{
    #pragma unroll
    for (int i = 0; i < 2; i++) {
        int idx = tid + i * 256;
        int row = idx >> 2, c16 = idx & 3;
        int gm = m0 + row; if (gm >= Arows) gm = Arows - 1;
        CP_ASYNC16(a_st + (row * BKP + c16 * 8) * 2, A + (size_t)gm * lda + k0 + c16 * 8);
    }
    #pragma unroll
    for (int i = 0; i < 4; i++) {
        int idx = tid + i * 256;
        int row = idx >> 2, c16 = idx & 3;
        int gn = n0 + row; if (gn >= Brows) gn = Brows - 1;
        CP_ASYNC16(b_st + (row * BKP + c16 * 8) * 2, B + (size_t)gn * ldb + k0 + c16 * 8);
    }
}

// ---------------- small kernels ----------------
__global__ void zero_acc_k(int total) {
    int i = blockIdx.x * blockDim.x + threadIdx.x;
    if (i < 16) g_acc[i] = 0.0f;
    if (i < total) { g_se[i] = 0.0f; g_sl[i] = 0.0f; }
}

__global__ void cvt_bf16_k(const float* __restrict__ src, __nv_bfloat16* __restrict__ dst, int n) {
    int i = blockIdx.x * blockDim.x + threadIdx.x;
    if (i * 4 < n) {
        float4 v = *(const float4*)(src + i * 4);
        __nv_bfloat16 o[4] = {__float2bfloat16_rn(v.x), __float2bfloat16_rn(v.y),
                              __float2bfloat16_rn(v.z), __float2bfloat16_rn(v.w)};
        *(uint64_t*)(dst + i * 4) = *(uint64_t*)o;
    }
}

// pack all 4 heads' W (transposed, bf16) + biases in one kernel
__global__ void cvt_w_all_k(const float* __restrict__ Ws, const float* __restrict__ bs,
                            const float* __restrict__ Wp, const float* __restrict__ bp,
                            const float* __restrict__ Wm, const float* __restrict__ bm,
                            const float* __restrict__ Wa, const float* __restrict__ ba) {
    int t = blockIdx.x * blockDim.x + threadIdx.x;
    if (t < HTOT * DMODEL) {
        int n = t / DMODEL, k = t % DMODEL;
        const float* W; int Dh, off;
        if (n < 256)      { W = Ws; Dh = 256; off = 0; }
        else if (n < 384) { W = Wp; Dh = 128; off = 256; }
        else if (n < 512) { W = Wm; Dh = 128; off = 384; }
        else              { W = Wa; Dh = 128; off = 512; }
        g_Wb[(size_t)n * DMODEL + k] = __float2bfloat16_rn(W[(size_t)k * Dh + (n - off)]);
    }
    if (t < HTOT) {
        const float* b; int off;
        if (t < 256)      { b = bs; off = 0; }
        else if (t < 384) { b = bp; off = 256; }
        else if (t < 512) { b = bm; off = 384; }
        else              { b = ba; off = 512; }
        g_bc[t] = b[t - off];
    }
}

__global__ void gather_x_k(const float* __restrict__ hid, const int* __restrict__ hsel) {
    int i = blockIdx.x;
    int idx = hsel[i];
    int s = idx % SSEQ;
    int n = idx / SSEQ;
    float4 v = ((const float4*)(hid + ((size_t)s * NSEQ + n) * DMODEL))[threadIdx.x];
    __nv_bfloat16 o[4] = {__float2bfloat16_rn(v.x), __float2bfloat16_rn(v.y),
                          __float2bfloat16_rn(v.z), __float2bfloat16_rn(v.w)};
    *(uint64_t*)(g_Xb + (size_t)i * DMODEL + threadIdx.x * 4) = *(uint64_t*)o;
}

// ---------------- transform GEMM (bf16 TC): g_H = gelu(Xb @ Wb^T + bc), out stride 640 ----
__global__ void __launch_bounds__(256)
gemm_tc_gelu(int M) {
    __shared__ __align__(16) __nv_bfloat16 As[2][128 * BKP];
    __shared__ __align__(16) __nv_bfloat16 Bs[2][128 * BKP];
    int m0 = blockIdx.y * 128, n0 = blockIdx.x * 128;
    int tid = threadIdx.x;
    int warp = tid >> 5, lane = tid & 31;
    int wm = warp >> 2, wn = warp & 3;
    int gr = lane >> 2, gc = lane & 3;

    uint32_t a_base = (uint32_t)__cvta_generic_to_shared(&As[0][0]);
    uint32_t b_base = (uint32_t)__cvta_generic_to_shared(&Bs[0][0]);
    const uint32_t STAGE = 128 * BKP * 2;

    float acc[4][4][4];
    #pragma unroll
    for (int mf = 0; mf < 4; mf++)
        #pragma unroll
        for (int nf = 0; nf < 4; nf++)
            #pragma unroll
            for (int q = 0; q < 4; q++) acc[mf][nf][q] = 0.0f;

    const int nc = DMODEL / 32;   // 24
    load_tile_pair(g_Xb, DMODEL, M, m0, g_Wb, DMODEL, HTOT, n0, 0, a_base, b_base, tid);
    CP_COMMIT();

    int a_row_off = wm * 64 + ((lane >> 3) & 1) * 8 + (lane & 7);
    int a_col     = (lane >> 4) * 8;
    int b_row_off = wn * 32 + ((lane >> 4) & 1) * 8 + (lane & 7);
    int b_col     = ((lane >> 3) & 1) * 8;

    for (int c = 0; c < nc; c++) {
        int cur = c & 1;
        if (c + 1 < nc)
            load_tile_pair(g_Xb, DMODEL, M, m0, g_Wb, DMODEL, HTOT, n0,
                           (c + 1) << 5, a_base + (cur ^ 1) * STAGE, b_base + (cur ^ 1) * STAGE, tid);
        CP_COMMIT();
        CP_WAIT1();
        __syncthreads();
        uint32_t abase_s = a_base + cur * STAGE;
        uint32_t bbase_s = b_base + cur * STAGE;
        #pragma unroll
        for (int ks = 0; ks < 2; ks++) {
            uint32_t af[4][4], bf[2][4];
            #pragma unroll
            for (int mf = 0; mf < 4; mf++)
                ldsm_x4(af[mf], abase_s + ((a_row_off + mf * 16) * BKP + a_col + ks * 16) * 2);
            #pragma unroll
            for (int p = 0; p < 2; p++)
                ldsm_x4(bf[p], bbase_s + ((b_row_off + p * 16) * BKP + b_col + ks * 16) * 2);
            #pragma unroll
            for (int mf = 0; mf < 4; mf++)
                #pragma unroll
                for (int nf = 0; nf < 4; nf++)
                    mma_bf16(acc[mf][nf], af[mf], &bf[nf >> 1][(nf & 1) * 2]);
        }
        __syncthreads();
    }

    #pragma unroll
    for (int mf = 0; mf < 4; mf++) {
        #pragma unroll
        for (int h = 0; h < 2; h++) {
            int grow = m0 + wm * 64 + mf * 16 + h * 8 + gr;
            if (grow < M) {
                #pragma unroll
                for (int nf = 0; nf < 4; nf++) {
                    int col = n0 + wn * 32 + nf * 8 + gc * 2;
                    float z0 = acc[mf][nf][h * 2 + 0] + g_bc[col];
                    float z1 = acc[mf][nf][h * 2 + 1] + g_bc[col + 1];
                    float y0 = 0.5f * z0 * (1.0f + erff(z0 * 0.70710678118654752f));
                    float y1 = 0.5f * z1 * (1.0f + erff(z1 * 0.70710678118654752f));
                    *(float2*)(g_H + (size_t)grow * HTOT + col) = make_float2(y0, y1);
                }
            }
        }
    }
}

// ---------------- warp-per-row LayerNorm on g_H segment [hoff, hoff+DH) -------------------
template <int DH>
__global__ void ln_warp_k(const float* __restrict__ g, const float* __restrict__ beta,
                          int hoff, int T) {
    int w = threadIdx.x >> 5, lane = threadIdx.x & 31;
    int row = blockIdx.x * 8 + w;
    if (row >= T) return;
    const int E = DH / 32;
    float* base = g_H + (size_t)row * HTOT + hoff;
    float v[E];
    float s = 0.f;
    #pragma unroll
    for (int i = 0; i < E; i++) { v[i] = base[lane + i * 32]; s += v[i]; }
    #pragma unroll
    for (int o = 16; o > 0; o >>= 1) s += __shfl_xor_sync(0xffffffffu, s, o);
    float mean = s / (float)DH;
    float q = 0.f;
    #pragma unroll
    for (int i = 0; i < E; i++) { float d = v[i] - mean; q += d * d; }
    #pragma unroll
    for (int o = 16; o > 0; o >>= 1) q += __shfl_xor_sync(0xffffffffu, q, o);
    float r = rsqrtf(q / (float)DH + 1e-12f);
    #pragma unroll
    for (int i = 0; i < E; i++) {
        float y = (v[i] - mean) * r * g[lane + i * 32] + beta[lane + i * 32];
        base[lane + i * 32] = y;
        g_Hb[(size_t)row * HTOT + hoff + lane + i * 32] = __float2bfloat16_rn(y);
    }
}

// ---------------- stats GEMM: BM=128 BN=256, warp tile 64x64, 4-stage, 1 CTA/SM -----------
// logits z[i,v] = Hb[i,:].Eb[v,:] + bias[v]; max-free: atomicAdd sum(exp z), sum(z) per row.
__global__ void __launch_bounds__(256)
gemm_nt_stats_bf16(const __nv_bfloat16* __restrict__ A, int lda,
                   const float* __restrict__ vbias, int M, int V, int K, int head) {
    extern __shared__ __align__(16) char dyn[];
    float* s_s   = (float*)(dyn + NSTAGE * (ASTG + BSTG));
    float* s_l   = s_s + 4 * 128;
    float* s_bias = s_l + 4 * 128;

    int m0 = blockIdx.y * 128, n0 = blockIdx.x * 256;
    int tid = threadIdx.x;
    int warp = tid >> 5, lane = tid & 31;
    int wm = warp >> 2, wn = warp & 3;     // 2 x 4 warp grid, warp tile 64x64
    int gr = lane >> 2, gc = lane & 3;

    if (tid < 256) {
        int v = n0 + tid;
        s_bias[tid] = (v < V) ? vbias[v] : 0.0f;
    }

    uint32_t a_base = (uint32_t)__cvta_generic_to_shared(dyn);
    uint32_t b_base = a_base + NSTAGE * ASTG;

    float acc[4][8][4];
    #pragma unroll
    for (int mf = 0; mf < 4; mf++)
        #pragma unroll
        for (int nf = 0; nf < 8; nf++)
            #pragma unroll
            for (int q = 0; q < 4; q++) acc[mf][nf][q] = 0.0f;

    int nc = K >> 5;

    #pragma unroll
    for (int s = 0; s < NSTAGE - 1; s++) {
        if (s < nc)
            load_tile_128_256(A, lda, M, m0, g_Eb, K, V, n0, s << 5,
                              a_base + s * ASTG, b_base + s * BSTG, tid);
        CP_COMMIT();
    }

    int a_row_off = wm * 64 + ((lane >> 3) & 1) * 8 + (lane & 7);
    int a_col     = (lane >> 4) * 8;
    int b_row_off = wn * 64 + ((lane >> 4) & 1) * 8 + (lane & 7);
    int b_col     = ((lane >> 3) & 1) * 8;

    for (int c = 0; c < nc; c++) {
        CP_WAIT2();
        __syncthreads();
        int cur = c & (NSTAGE - 1);
        uint32_t abase_s = a_base + cur * ASTG;
        uint32_t bbase_s = b_base + cur * BSTG;
        #pragma unroll
        for (int ks = 0; ks < 2; ks++) {
            uint32_t af[4][4], bf[4][4];
            #pragma unroll
            for (int mf = 0; mf < 4; mf++)
                ldsm_x4(af[mf], abase_s + ((a_row_off + mf * 16) * BKP + a_col + ks * 16) * 2);
            #pragma unroll
            for (int p = 0; p < 4; p++)
                ldsm_x4(bf[p], bbase_s + ((b_row_off + p * 16) * BKP + b_col + ks * 16) * 2);
            #pragma unroll
            for (int mf = 0; mf < 4; mf++)
                #pragma unroll
                for (int nf = 0; nf < 8; nf++)
                    mma_bf16(acc[mf][nf], af[mf], &bf[nf >> 1][(nf & 1) * 2]);
        }
        int nxt = c + NSTAGE - 1;
        if (nxt < nc) {
            int st = nxt & (NSTAGE - 1);
            load_tile_128_256(A, lda, M, m0, g_Eb, K, V, n0, nxt << 5,
                              a_base + st * ASTG, b_base + st * BSTG, tid);
        }
        CP_COMMIT();
    }

    // epilogue: per-row sum(exp z), sum(z) over this block's 256 columns (max-free)
    __syncthreads();
    #pragma unroll
    for (int mf = 0; mf < 4; mf++) {
        #pragma unroll
        for (int h = 0; h < 2; h++) {
            int rowb = wm * 64 + mf * 16 + h * 8 + gr;
            float sloc = 0.f, slloc = 0.f;
            #pragma unroll
            for (int nf = 0; nf < 8; nf++) {
                #pragma unroll
                for (int q = 0; q < 2; q++) {
                    int colb = wn * 64 + nf * 8 + gc * 2 + q;
                    if (n0 + colb < V) {
                        float z = acc[mf][nf][h * 2 + q] + s_bias[colb];
                        sloc += __expf(z);
                        slloc += z;
                    }
                }
            }
            sloc  += __shfl_xor_sync(0xffffffffu, sloc, 1);
            sloc  += __shfl_xor_sync(0xffffffffu, sloc, 2);
            slloc += __shfl_xor_sync(0xffffffffu, slloc, 1);
            slloc += __shfl_xor_sync(0xffffffffu, slloc, 2);
            if (gc == 0) {
                s_s[wn * 128 + rowb] = sloc;
                s_l[wn * 128 + rowb] = slloc;
            }
        }
    }
    __syncthreads();
    if (tid < 128) {
        int grow = m0 + tid;
        if (grow < M) {
            float s = s_s[tid] + s_s[128 + tid] + s_s[256 + tid] + s_s[384 + tid];
            float sl = s_l[tid] + s_l[128 + tid] + s_l[256 + tid] + s_l[384 + tid];
            atomicAdd(&g_se[head * MAXT + grow], s);
            atomicAdd(&g_sl[head * MAXT + grow], sl);
        }
    }
}

// ---------------- per-row loss: logZ = log(sum exp), target logit dot, accumulate ----------
__global__ void reduce_softmax_k(const float* __restrict__ vbias,
                                 const int* __restrict__ labels, const int* __restrict__ tsel,
                                 int V, int K, int hoff, int head, int accoff) {
    int row = blockIdx.x;
    int tid = threadIdx.x;   // 128 threads
    __shared__ float sd[128];
    int tgt = labels[tsel[row]];
    float d = 0.f;
    for (int k = tid; k < K; k += 128)
        d += __bfloat162float(g_Hb[(size_t)row * HTOT + hoff + k]) *
             __bfloat162float(g_Eb[(size_t)tgt * K + k]);
    sd[tid] = d; __syncthreads();
    for (int o = 64; o > 0; o >>= 1) { if (tid < o) sd[tid] += sd[tid + o]; __syncthreads(); }
    if (tid == 0) {
        float logZ = logf(g_se[head * MAXT + row]);
        float tlogit = sd[0] + vbias[tgt];
        float nll = logZ - tlogit;
        float smooth = (float)V * logZ - g_sl[head * MAXT + row];
        atomicAdd(&g_acc[accoff], nll);
        atomicAdd(&g_acc[accoff + 1], smooth);
    }
}

// ---------------- affix head: z = H[asel]@emb^T + bias, fused BCE-with-logits sum ----------
__global__ void gemm_nt_bce_k(const float* __restrict__ emb, const float* __restrict__ vbias,
                              const float* __restrict__ aprob, const int* __restrict__ tsel,
                              const int* __restrict__ asel, int M, int V, int K, int hoff) {
    __shared__ __align__(16) float As[16][68];
    __shared__ __align__(16) float Bs[16][68];
    __shared__ float red[256];
    int m0 = blockIdx.y * 64, n0 = blockIdx.x * 64;
    int tid = threadIdx.x;
    int tx = tid & 15, ty = tid >> 4;
    int lrow = tid >> 2, lk4 = (tid & 3) * 4;
    float acc[4][4] = {};
    for (int k0 = 0; k0 < K; k0 += 16) {
        float4 av = make_float4(0.f, 0.f, 0.f, 0.f);
        int ar = m0 + lrow;
        if (ar < M) {
            int pr = asel[ar];
            av = *(const float4*)(g_H + (size_t)pr * HTOT + hoff + k0 + lk4);
        }
        As[lk4 + 0][lrow] = av.x; As[lk4 + 1][lrow] = av.y;
        As[lk4 + 2][lrow] = av.z; As[lk4 + 3][lrow] = av.w;
        float4 bv = make_float4(0.f, 0.f, 0.f, 0.f);
        int br = n0 + lrow;
        if (br < V) bv = *(const float4*)(emb + (size_t)br * K + k0 + lk4);
        Bs[lk4 + 0][lrow] = bv.x; Bs[lk4 + 1][lrow] = bv.y;
        Bs[lk4 + 2][lrow] = bv.z; Bs[lk4 + 3][lrow] = bv.w;
        __syncthreads();
        #pragma unroll
        for (int k = 0; k < 16; k++) {
            float4 a4 = *(const float4*)&As[k][ty * 4];
            float4 b4 = *(const float4*)&Bs[k][tx * 4];
            float a_[4] = {a4.x, a4.y, a4.z, a4.w};
            float b_[4] = {b4.x, b4.y, b4.z, b4.w};
            #pragma unroll
            for (int r = 0; r < 4; r++)
                #pragma unroll
                for (int c = 0; c < 4; c++) acc[r][c] += a_[r] * b_[c];
        }
        __syncthreads();
    }
    float lsum = 0.f;
    #pragma unroll
    for (int r = 0; r < 4; r++) {
        int grow = m0 + ty * 4 + r;
        if (grow < M) {
            int trow = tsel[asel[grow]];
            #pragma unroll
            for (int c = 0; c < 4; c++) {
                int v = n0 + tx * 4 + c;
                if (v < V) {
                    float z = acc[r][c] + vbias[v];
                    float t = aprob[(size_t)trow * 360 + v];
                    lsum += fmaxf(z, 0.f) - z * t + log1pf(__expf(-fabsf(z)));
                }
            }
        }
    }
    red[tid] = lsum; __syncthreads();
    for (int o = 128; o > 0; o >>= 1) { if (tid < o) red[tid] += red[tid + o]; __syncthreads(); }
    if (tid == 0) atomicAdd(&g_acc[6], red[0]);
}

// ---------------- finalize: assemble the 7 output scalars ----------------
__global__ void finalize_k(float* __restrict__ out, int T, int Ta) {
    if (threadIdx.x != 0 || blockIdx.x != 0) return;
    const int Vs[3] = {50000, 200, 400};
    for (int h = 0; h < 3; h++) {
        float nll_m = g_acc[2 * h] / (float)T;
        float sm_m  = g_acc[2 * h + 1] / (float)T;
        float eps_i = 0.1f / (float)(Vs[h] - 1);
        out[h] = (1.0f - 0.1f - eps_i) * nll_m + eps_i * sm_m;
        out[4 + h] = nll_m;
    }
    out[3] = g_acc[6] / ((float)Ta * 360.0f);
}

// ---------------- launch ----------------
extern "C" void kernel_launch(void* const* d_in, const int* in_sizes, int n_in,
                              void* d_out, int out_size) {
    const float* hid    = (const float*)d_in[0];
    const float* aprob  = (const float*)d_in[1];
    const int* stems    = (const int*)d_in[2];
    const int* postags  = (const int*)d_in[3];
    const int* morphs   = (const int*)d_in[4];
    const int* hsel     = (const int*)d_in[5];
    const int* tsel     = (const int*)d_in[6];
    const int* asel     = (const int*)d_in[7];
    const float* stem_emb  = (const float*)d_in[8];
    const float* stem_W    = (const float*)d_in[9];
    const float* stem_b    = (const float*)d_in[10];
    const float* stem_g    = (const float*)d_in[11];
    const float* stem_beta = (const float*)d_in[12];
    const float* stem_bias = (const float*)d_in[13];
    const float* pos_emb   = (const float*)d_in[14];
    const float* pos_W     = (const float*)d_in[15];
    const float* pos_b     = (const float*)d_in[16];
    const float* pos_g     = (const float*)d_in[17];
    const float* pos_beta  = (const float*)d_in[18];
    const float* pos_bias  = (const float*)d_in[19];
    const float* morph_emb = (const float*)d_in[20];
    const float* morph_W   = (const float*)d_in[21];
    const float* morph_b   = (const float*)d_in[22];
    const float* morph_g   = (const float*)d_in[23];
    const float* morph_beta= (const float*)d_in[24];
    const float* morph_bias= (const float*)d_in[25];
    const float* aff_emb   = (const float*)d_in[26];
    const float* aff_W     = (const float*)d_in[27];
    const float* aff_b     = (const float*)d_in[28];
    const float* aff_g     = (const float*)d_in[29];
    const float* aff_beta  = (const float*)d_in[30];
    const float* aff_bias  = (const float*)d_in[31];
    float* out = (float*)d_out;

    int T  = in_sizes[5];
    int Ta = in_sizes[7];
    int mT128 = (T + 127) / 128;
    int mTa = (Ta + 63) / 64;
    int lnb = (T + 7) / 8;

    __nv_bfloat16* dEb;
    __nv_bfloat16* dHb;
    cudaGetSymbolAddress((void**)&dEb, g_Eb);
    cudaGetSymbolAddress((void**)&dHb, g_Hb);

    cudaFuncSetAttribute(gemm_nt_stats_bf16,
                         cudaFuncAttributeMaxDynamicSharedMemorySize, SMEM_STATS);

    zero_acc_k<<<(4 * MAXT + 255) / 256, 256>>>(4 * MAXT);
    gather_x_k<<<T, 192>>>(hid, hsel);

    cvt_w_all_k<<<(HTOT * DMODEL + 255) / 256, 256>>>(stem_W, stem_b, pos_W, pos_b,
                                                      morph_W, morph_b, aff_W, aff_b);

    gemm_tc_gelu<<<dim3(HTOT / 128, mT128), 256>>>(T);

    ln_warp_k<256><<<lnb, 256>>>(stem_g,  stem_beta,  0,   T);
    ln_warp_k<128><<<lnb, 256>>>(pos_g,   pos_beta,   256, T);
    ln_warp_k<128><<<lnb, 256>>>(morph_g, morph_beta, 384, T);
    ln_warp_k<128><<<lnb, 256>>>(aff_g,   aff_beta,   512, T);

    // ---- stem head: Dh=256, V=50000 ----
    {
        const int Dh = 256, V = 50000, nvb = (V + 255) / 256;
        cvt_bf16_k<<<(V * Dh / 4 + 255) / 256, 256>>>(stem_emb, dEb, V * Dh);
        gemm_nt_stats_bf16<<<dim3(nvb, mT128), 256, SMEM_STATS>>>(dHb + 0, HTOT, stem_bias, T, V, Dh, 0);
        reduce_softmax_k<<<T, 128>>>(stem_bias, stems, tsel, V, Dh, 0, 0, 0);
    }
    // ---- pos head: Dh=128, V=200 ----
    {
        const int Dh = 128, V = 200, nvb = (V + 255) / 256;
        cvt_bf16_k<<<(V * Dh / 4 + 255) / 256, 256>>>(pos_emb, dEb, V * Dh);
        gemm_nt_stats_bf16<<<dim3(nvb, mT128), 256, SMEM_STATS>>>(dHb + 256, HTOT, pos_bias, T, V, Dh, 1);
        reduce_softmax_k<<<T, 128>>>(pos_bias, postags, tsel, V, Dh, 256, 1, 2);
    }
    // ---- morph head: Dh=128, V=400 ----
    {
        const int Dh = 128, V = 400, nvb = (V + 255) / 256;
        cvt_bf16_k<<<(V * Dh / 4 + 255) / 256, 256>>>(morph_emb, dEb, V * Dh);
        gemm_nt_stats_bf16<<<dim3(nvb, mT128), 256, SMEM_STATS>>>(dHb + 384, HTOT, morph_bias, T, V, Dh, 2);
        reduce_softmax_k<<<T, 128>>>(morph_bias, morphs, tsel, V, Dh, 384, 2, 4);
    }
    // ---- affix head: Dh=128, V=360, rows = H[asel[i]], BCE ----
    {
        const int Dh = 128, V = 360;
        gemm_nt_bce_k<<<dim3((V + 63) / 64, mTa), 256>>>(aff_emb, aff_bias, aprob, tsel, asel,
                                                         Ta, V, Dh, 512);
    }

    finalize_k<<<1, 32>>>(out, T, Ta);
}

// round 11
// speedup vs baseline: 1.3833x; 1.3833x over previous
#include <cuda_runtime.h>
#include <cuda_bf16.h>
#include <math.h>
#include <stdint.h>
#include <stddef.h>

// ---------------- problem constants ----------------
#define NSEQ 8
#define SSEQ 448
#define DMODEL 768
#define MAXT 3584          // >= N*(S-1) = 3576
#define MAXV 50000
#define HTOT 640           // 256 + 128 + 128 + 128 concatenated head dims

// ---------------- device scratch (no allocs allowed) ----------------
__device__ __nv_bfloat16 g_Xb[MAXT * DMODEL];        // gathered predictor states bf16
__device__ __nv_bfloat16 g_Wb[HTOT * DMODEL];        // W^T concat bf16: [n=640][k=768]
__device__ float g_bc[HTOT];                         // concatenated transform biases
__device__ float g_H[MAXT * HTOT];                   // transform output fp32 (post-gelu/LN)
__device__ __nv_bfloat16 g_Hb[MAXT * HTOT];          // bf16 copy of H (post-LN)
__device__ __nv_bfloat16 g_Eb[MAXV * 256];           // bf16 copy of current head's emb
__device__ float g_se[4 * MAXT];                     // per-head per-row sum(exp(z))
__device__ float g_sl[4 * MAXT];                     // per-head per-row sum(z)
__device__ float g_acc[16];                          // loss accumulators

// ---------------- asm helpers ----------------
#define CP_ASYNC16(dst, src) \
    asm volatile("cp.async.cg.shared.global [%0], [%1], 16;\n" :: "r"(dst), "l"(src))
#define CP_COMMIT() asm volatile("cp.async.commit_group;\n" ::)
#define CP_WAIT1()  asm volatile("cp.async.wait_group 1;\n" ::)
#define CP_WAIT2()  asm volatile("cp.async.wait_group 2;\n" ::)

__device__ __forceinline__ void ldsm_x4(uint32_t* r, uint32_t addr) {
    asm volatile("ldmatrix.sync.aligned.m8n8.x4.shared.b16 {%0,%1,%2,%3}, [%4];"
                 : "=r"(r[0]), "=r"(r[1]), "=r"(r[2]), "=r"(r[3]) : "r"(addr));
}

__device__ __forceinline__ void mma_bf16(float* c, const uint32_t* a, const uint32_t* b) {
    asm volatile("mma.sync.aligned.m16n8k16.row.col.f32.bf16.bf16.f32 "
                 "{%0,%1,%2,%3}, {%4,%5,%6,%7}, {%8,%9}, {%0,%1,%2,%3};\n"
                 : "+f"(c[0]), "+f"(c[1]), "+f"(c[2]), "+f"(c[3])
                 : "r"(a[0]), "r"(a[1]), "r"(a[2]), "r"(a[3]), "r"(b[0]), "r"(b[1]));
}

#define BKP 40           // padded smem row stride in bf16 elements (80 bytes)
#define STAGE_B (128 * BKP * 2)   // 10240 bytes per operand per stage
#define NSTAGE 4
#define SMEM_STATS (NSTAGE * STAGE_B * 2 + 2 * 4 * 128 * 4 + 128 * 4)  // 86528 B

// stage loader: 128 rows x 32 cols of A and B (bf16), 4 cp.async/thread
__device__ __forceinline__ void load_tile_pair(
    const __nv_bfloat16* __restrict__ A, int lda, int Arows, int m0,
    const __nv_bfloat16* __restrict__ B, int ldb, int Brows, int n0,
    int k0, uint32_t a_st, uint32_t b_st, int tid)
{
    #pragma unroll
    for (int i = 0; i < 2; i++) {
        int idx = tid + i * 256;
        int row = idx >> 2, c16 = idx & 3;
        int gm = m0 + row; if (gm >= Arows) gm = Arows - 1;
        CP_ASYNC16(a_st + (row * BKP + c16 * 8) * 2, A + (size_t)gm * lda + k0 + c16 * 8);
        int gn = n0 + row; if (gn >= Brows) gn = Brows - 1;
        CP_ASYNC16(b_st + (row * BKP + c16 * 8) * 2, B + (size_t)gn * ldb + k0 + c16 * 8);
    }
}

// ---------------- small kernels ----------------
__global__ void cvt_bf16_k(const float* __restrict__ src, __nv_bfloat16* __restrict__ dst, int n) {
    int i = blockIdx.x * blockDim.x + threadIdx.x;
    if (i * 4 < n) {
        float4 v = *(const float4*)(src + i * 4);
        __nv_bfloat16 o[4] = {__float2bfloat16_rn(v.x), __float2bfloat16_rn(v.y),
                              __float2bfloat16_rn(v.z), __float2bfloat16_rn(v.w)};
        *(uint64_t*)(dst + i * 4) = *(uint64_t*)o;
    }
}

// pack all 4 heads' W (transposed bf16) + biases + zero the accumulators, one kernel
__global__ void cvt_w_all_k(const float* __restrict__ Ws, const float* __restrict__ bs,
                            const float* __restrict__ Wp, const float* __restrict__ bp,
                            const float* __restrict__ Wm, const float* __restrict__ bm,
                            const float* __restrict__ Wa, const float* __restrict__ ba) {
    int t = blockIdx.x * blockDim.x + threadIdx.x;
    if (t < HTOT * DMODEL) {
        int n = t / DMODEL, k = t % DMODEL;
        const float* W; int Dh, off;
        if (n < 256)      { W = Ws; Dh = 256; off = 0; }
        else if (n < 384) { W = Wp; Dh = 128; off = 256; }
        else if (n < 512) { W = Wm; Dh = 128; off = 384; }
        else              { W = Wa; Dh = 128; off = 512; }
        g_Wb[(size_t)n * DMODEL + k] = __float2bfloat16_rn(W[(size_t)k * Dh + (n - off)]);
    }
    if (t < HTOT) {
        const float* b; int off;
        if (t < 256)      { b = bs; off = 0; }
        else if (t < 384) { b = bp; off = 256; }
        else if (t < 512) { b = bm; off = 384; }
        else              { b = ba; off = 512; }
        g_bc[t] = b[t - off];
    }
    if (t < 16) g_acc[t] = 0.0f;
    if (t < 4 * MAXT) { g_se[t] = 0.0f; g_sl[t] = 0.0f; }
}

__global__ void gather_x_k(const float* __restrict__ hid, const int* __restrict__ hsel) {
    int i = blockIdx.x;
    int idx = hsel[i];
    int s = idx % SSEQ;
    int n = idx / SSEQ;
    float4 v = ((const float4*)(hid + ((size_t)s * NSEQ + n) * DMODEL))[threadIdx.x];
    __nv_bfloat16 o[4] = {__float2bfloat16_rn(v.x), __float2bfloat16_rn(v.y),
                          __float2bfloat16_rn(v.z), __float2bfloat16_rn(v.w)};
    *(uint64_t*)(g_Xb + (size_t)i * DMODEL + threadIdx.x * 4) = *(uint64_t*)o;
}

// ---------------- transform GEMM (bf16 TC): g_H = gelu(Xb @ Wb^T + bc), out stride 640 ----
__global__ void __launch_bounds__(256)
gemm_tc_gelu(int M) {
    __shared__ __align__(16) __nv_bfloat16 As[2][128 * BKP];
    __shared__ __align__(16) __nv_bfloat16 Bs[2][128 * BKP];
    int m0 = blockIdx.y * 128, n0 = blockIdx.x * 128;
    int tid = threadIdx.x;
    int warp = tid >> 5, lane = tid & 31;
    int wm = warp >> 2, wn = warp & 3;
    int gr = lane >> 2, gc = lane & 3;

    uint32_t a_base = (uint32_t)__cvta_generic_to_shared(&As[0][0]);
    uint32_t b_base = (uint32_t)__cvta_generic_to_shared(&Bs[0][0]);
    const uint32_t STAGE = 128 * BKP * 2;

    float acc[4][4][4];
    #pragma unroll
    for (int mf = 0; mf < 4; mf++)
        #pragma unroll
        for (int nf = 0; nf < 4; nf++)
            #pragma unroll
            for (int q = 0; q < 4; q++) acc[mf][nf][q] = 0.0f;

    const int nc = DMODEL / 32;   // 24
    load_tile_pair(g_Xb, DMODEL, M, m0, g_Wb, DMODEL, HTOT, n0, 0, a_base, b_base, tid);
    CP_COMMIT();

    int a_row_off = wm * 64 + ((lane >> 3) & 1) * 8 + (lane & 7);
    int a_col     = (lane >> 4) * 8;
    int b_row_off = wn * 32 + ((lane >> 4) & 1) * 8 + (lane & 7);
    int b_col     = ((lane >> 3) & 1) * 8;

    for (int c = 0; c < nc; c++) {
        int cur = c & 1;
        if (c + 1 < nc)
            load_tile_pair(g_Xb, DMODEL, M, m0, g_Wb, DMODEL, HTOT, n0,
                           (c + 1) << 5, a_base + (cur ^ 1) * STAGE, b_base + (cur ^ 1) * STAGE, tid);
        CP_COMMIT();
        CP_WAIT1();
        __syncthreads();
        uint32_t abase_s = a_base + cur * STAGE;
        uint32_t bbase_s = b_base + cur * STAGE;
        #pragma unroll
        for (int ks = 0; ks < 2; ks++) {
            uint32_t af[4][4], bf[2][4];
            #pragma unroll
            for (int mf = 0; mf < 4; mf++)
                ldsm_x4(af[mf], abase_s + ((a_row_off + mf * 16) * BKP + a_col + ks * 16) * 2);
            #pragma unroll
            for (int p = 0; p < 2; p++)
                ldsm_x4(bf[p], bbase_s + ((b_row_off + p * 16) * BKP + b_col + ks * 16) * 2);
            #pragma unroll
            for (int mf = 0; mf < 4; mf++)
                #pragma unroll
                for (int nf = 0; nf < 4; nf++)
                    mma_bf16(acc[mf][nf], af[mf], &bf[nf >> 1][(nf & 1) * 2]);
        }
        __syncthreads();
    }

    #pragma unroll
    for (int mf = 0; mf < 4; mf++) {
        #pragma unroll
        for (int h = 0; h < 2; h++) {
            int grow = m0 + wm * 64 + mf * 16 + h * 8 + gr;
            if (grow < M) {
                #pragma unroll
                for (int nf = 0; nf < 4; nf++) {
                    int col = n0 + wn * 32 + nf * 8 + gc * 2;
                    float z0 = acc[mf][nf][h * 2 + 0] + g_bc[col];
                    float z1 = acc[mf][nf][h * 2 + 1] + g_bc[col + 1];
                    float y0 = 0.5f * z0 * (1.0f + erff(z0 * 0.70710678118654752f));
                    float y1 = 0.5f * z1 * (1.0f + erff(z1 * 0.70710678118654752f));
                    *(float2*)(g_H + (size_t)grow * HTOT + col) = make_float2(y0, y1);
                }
            }
        }
    }
}

// ---------------- merged LayerNorm: one warp per (row, head) task, 4T tasks ---------------
__global__ void ln_all_k(const float* __restrict__ gs, const float* __restrict__ bts,
                         const float* __restrict__ gp, const float* __restrict__ btp,
                         const float* __restrict__ gm, const float* __restrict__ btm,
                         const float* __restrict__ ga, const float* __restrict__ bta,
                         int T) {
    int w = threadIdx.x >> 5, lane = threadIdx.x & 31;
    int task = blockIdx.x * 8 + w;
    if (task >= 4 * T) return;
    int head = task / T;          // uniform per warp
    int row = task - head * T;
    int hoff, DH;
    const float* g; const float* bt;
    if (head == 0)      { hoff = 0;   DH = 256; g = gs; bt = bts; }
    else if (head == 1) { hoff = 256; DH = 128; g = gp; bt = btp; }
    else if (head == 2) { hoff = 384; DH = 128; g = gm; bt = btm; }
    else                { hoff = 512; DH = 128; g = ga; bt = bta; }
    int E = DH >> 5;              // 4 or 8
    float* base = g_H + (size_t)row * HTOT + hoff;
    float v[8];
    float s = 0.f;
    for (int i = 0; i < E; i++) { v[i] = base[lane + i * 32]; s += v[i]; }
    #pragma unroll
    for (int o = 16; o > 0; o >>= 1) s += __shfl_xor_sync(0xffffffffu, s, o);
    float mean = s / (float)DH;
    float q = 0.f;
    for (int i = 0; i < E; i++) { float d = v[i] - mean; q += d * d; }
    #pragma unroll
    for (int o = 16; o > 0; o >>= 1) q += __shfl_xor_sync(0xffffffffu, q, o);
    float r = rsqrtf(q / (float)DH + 1e-12f);
    for (int i = 0; i < E; i++) {
        float y = (v[i] - mean) * r * g[lane + i * 32] + bt[lane + i * 32];
        base[lane + i * 32] = y;
        g_Hb[(size_t)row * HTOT + hoff + lane + i * 32] = __float2bfloat16_rn(y);
    }
}

// ---------------- stats GEMM (bf16 TC, 4-stage cp.async, 2 CTA/SM, dynamic smem) ----------
// logits z[i,v] = Hb[i,:].Eb[v,:] + bias[v]; max-free: atomicAdd sum(exp z), sum(z) per row.
// (|z| <= ~2 here: H is LN'd, emb entries ~0.02, so exp never overflows.)
__global__ void __launch_bounds__(256, 2)
gemm_nt_stats_bf16(const __nv_bfloat16* __restrict__ A, int lda,
                   const float* __restrict__ vbias, int M, int V, int K, int head) {
    extern __shared__ __align__(16) char dyn[];
    float* s_s   = (float*)(dyn + NSTAGE * STAGE_B * 2);
    float* s_l   = s_s + 4 * 128;
    float* s_bias = s_l + 4 * 128;

    int m0 = blockIdx.y * 128, n0 = blockIdx.x * 128;
    int tid = threadIdx.x;
    int warp = tid >> 5, lane = tid & 31;
    int wm = warp >> 2, wn = warp & 3;
    int gr = lane >> 2, gc = lane & 3;

    if (tid < 128) {
        int v = n0 + tid;
        s_bias[tid] = (v < V) ? vbias[v] : 0.0f;
    }

    uint32_t a_base = (uint32_t)__cvta_generic_to_shared(dyn);
    uint32_t b_base = a_base + NSTAGE * STAGE_B;

    float acc[4][4][4];
    #pragma unroll
    for (int mf = 0; mf < 4; mf++)
        #pragma unroll
        for (int nf = 0; nf < 4; nf++)
            #pragma unroll
            for (int q = 0; q < 4; q++) acc[mf][nf][q] = 0.0f;

    int nc = K >> 5;

    #pragma unroll
    for (int s = 0; s < NSTAGE - 1; s++) {
        if (s < nc)
            load_tile_pair(A, lda, M, m0, g_Eb, K, V, n0, s << 5,
                           a_base + s * STAGE_B, b_base + s * STAGE_B, tid);
        CP_COMMIT();
    }

    int a_row_off = wm * 64 + ((lane >> 3) & 1) * 8 + (lane & 7);
    int a_col     = (lane >> 4) * 8;
    int b_row_off = wn * 32 + ((lane >> 4) & 1) * 8 + (lane & 7);
    int b_col     = ((lane >> 3) & 1) * 8;

    for (int c = 0; c < nc; c++) {
        CP_WAIT2();
        __syncthreads();
        int cur = c & (NSTAGE - 1);
        uint32_t abase_s = a_base + cur * STAGE_B;
        uint32_t bbase_s = b_base + cur * STAGE_B;
        #pragma unroll
        for (int ks = 0; ks < 2; ks++) {
            uint32_t af[4][4], bf[2][4];
            #pragma unroll
            for (int mf = 0; mf < 4; mf++)
                ldsm_x4(af[mf], abase_s + ((a_row_off + mf * 16) * BKP + a_col + ks * 16) * 2);
            #pragma unroll
            for (int p = 0; p < 2; p++)
                ldsm_x4(bf[p], bbase_s + ((b_row_off + p * 16) * BKP + b_col + ks * 16) * 2);
            #pragma unroll
            for (int mf = 0; mf < 4; mf++)
                #pragma unroll
                for (int nf = 0; nf < 4; nf++)
                    mma_bf16(acc[mf][nf], af[mf], &bf[nf >> 1][(nf & 1) * 2]);
        }
        int nxt = c + NSTAGE - 1;
        if (nxt < nc) {
            int st = nxt & (NSTAGE - 1);
            load_tile_pair(A, lda, M, m0, g_Eb, K, V, n0, nxt << 5,
                           a_base + st * STAGE_B, b_base + st * STAGE_B, tid);
        }
        CP_COMMIT();
    }

    // epilogue: per-row sum(exp z), sum(z) over this block's 128 columns (max-free)
    __syncthreads();
    #pragma unroll
    for (int mf = 0; mf < 4; mf++) {
        #pragma unroll
        for (int h = 0; h < 2; h++) {
            int rowb = wm * 64 + mf * 16 + h * 8 + gr;
            float sloc = 0.f, slloc = 0.f;
            #pragma unroll
            for (int nf = 0; nf < 4; nf++) {
                #pragma unroll
                for (int q = 0; q < 2; q++) {
                    int colb = wn * 32 + nf * 8 + gc * 2 + q;
                    if (n0 + colb < V) {
                        float z = acc[mf][nf][h * 2 + q] + s_bias[colb];
                        sloc += __expf(z);
                        slloc += z;
                    }
                }
            }
            sloc  += __shfl_xor_sync(0xffffffffu, sloc, 1);
            sloc  += __shfl_xor_sync(0xffffffffu, sloc, 2);
            slloc += __shfl_xor_sync(0xffffffffu, slloc, 1);
            slloc += __shfl_xor_sync(0xffffffffu, slloc, 2);
            if (gc == 0) {
                s_s[wn * 128 + rowb] = sloc;
                s_l[wn * 128 + rowb] = slloc;
            }
        }
    }
    __syncthreads();
    if (tid < 128) {
        int grow = m0 + tid;
        if (grow < M) {
            float s = s_s[tid] + s_s[128 + tid] + s_s[256 + tid] + s_s[384 + tid];
            float sl = s_l[tid] + s_l[128 + tid] + s_l[256 + tid] + s_l[384 + tid];
            atomicAdd(&g_se[head * MAXT + grow], s);
            atomicAdd(&g_sl[head * MAXT + grow], sl);
        }
    }
}

// ---------------- per-row loss: logZ = log(sum exp), target logit dot, accumulate ----------
__global__ void reduce_softmax_k(const float* __restrict__ vbias,
                                 const int* __restrict__ labels, const int* __restrict__ tsel,
                                 int V, int K, int hoff, int head, int accoff) {
    int row = blockIdx.x;
    int tid = threadIdx.x;   // 128 threads
    __shared__ float sd[128];
    int tgt = labels[tsel[row]];
    float d = 0.f;
    for (int k = tid; k < K; k += 128)
        d += __bfloat162float(g_Hb[(size_t)row * HTOT + hoff + k]) *
             __bfloat162float(g_Eb[(size_t)tgt * K + k]);
    sd[tid] = d; __syncthreads();
    for (int o = 64; o > 0; o >>= 1) { if (tid < o) sd[tid] += sd[tid + o]; __syncthreads(); }
    if (tid == 0) {
        float logZ = logf(g_se[head * MAXT + row]);
        float tlogit = sd[0] + vbias[tgt];
        float nll = logZ - tlogit;
        float smooth = (float)V * logZ - g_sl[head * MAXT + row];
        atomicAdd(&g_acc[accoff], nll);
        atomicAdd(&g_acc[accoff + 1], smooth);
    }
}

// ---------------- affix head: z = H[asel]@emb^T + bias, fused BCE-with-logits sum ----------
__global__ void gemm_nt_bce_k(const float* __restrict__ emb, const float* __restrict__ vbias,
                              const float* __restrict__ aprob, const int* __restrict__ tsel,
                              const int* __restrict__ asel, int M, int V, int K, int hoff) {
    __shared__ __align__(16) float As[16][68];
    __shared__ __align__(16) float Bs[16][68];
    __shared__ float red[256];
    int m0 = blockIdx.y * 64, n0 = blockIdx.x * 64;
    int tid = threadIdx.x;
    int tx = tid & 15, ty = tid >> 4;
    int lrow = tid >> 2, lk4 = (tid & 3) * 4;
    float acc[4][4] = {};
    for (int k0 = 0; k0 < K; k0 += 16) {
        float4 av = make_float4(0.f, 0.f, 0.f, 0.f);
        int ar = m0 + lrow;
        if (ar < M) {
            int pr = asel[ar];
            av = *(const float4*)(g_H + (size_t)pr * HTOT + hoff + k0 + lk4);
        }
        As[lk4 + 0][lrow] = av.x; As[lk4 + 1][lrow] = av.y;
        As[lk4 + 2][lrow] = av.z; As[lk4 + 3][lrow] = av.w;
        float4 bv = make_float4(0.f, 0.f, 0.f, 0.f);
        int br = n0 + lrow;
        if (br < V) bv = *(const float4*)(emb + (size_t)br * K + k0 + lk4);
        Bs[lk4 + 0][lrow] = bv.x; Bs[lk4 + 1][lrow] = bv.y;
        Bs[lk4 + 2][lrow] = bv.z; Bs[lk4 + 3][lrow] = bv.w;
        __syncthreads();
        #pragma unroll
        for (int k = 0; k < 16; k++) {
            float4 a4 = *(const float4*)&As[k][ty * 4];
            float4 b4 = *(const float4*)&Bs[k][tx * 4];
            float a_[4] = {a4.x, a4.y, a4.z, a4.w};
            float b_[4] = {b4.x, b4.y, b4.z, b4.w};
            #pragma unroll
            for (int r = 0; r < 4; r++)
                #pragma unroll
                for (int c = 0; c < 4; c++) acc[r][c] += a_[r] * b_[c];
        }
        __syncthreads();
    }
    float lsum = 0.f;
    #pragma unroll
    for (int r = 0; r < 4; r++) {
        int grow = m0 + ty * 4 + r;
        if (grow < M) {
            int trow = tsel[asel[grow]];
            #pragma unroll
            for (int c = 0; c < 4; c++) {
                int v = n0 + tx * 4 + c;
                if (v < V) {
                    float z = acc[r][c] + vbias[v];
                    float t = aprob[(size_t)trow * 360 + v];
                    lsum += fmaxf(z, 0.f) - z * t + log1pf(__expf(-fabsf(z)));
                }
            }
        }
    }
    red[tid] = lsum; __syncthreads();
    for (int o = 128; o > 0; o >>= 1) { if (tid < o) red[tid] += red[tid + o]; __syncthreads(); }
    if (tid == 0) atomicAdd(&g_acc[6], red[0]);
}

// ---------------- finalize: assemble the 7 output scalars ----------------
__global__ void finalize_k(float* __restrict__ out, int T, int Ta) {
    if (threadIdx.x != 0 || blockIdx.x != 0) return;
    const int Vs[3] = {50000, 200, 400};
    for (int h = 0; h < 3; h++) {
        float nll_m = g_acc[2 * h] / (float)T;
        float sm_m  = g_acc[2 * h + 1] / (float)T;
        float eps_i = 0.1f / (float)(Vs[h] - 1);
        out[h] = (1.0f - 0.1f - eps_i) * nll_m + eps_i * sm_m;
        out[4 + h] = nll_m;
    }
    out[3] = g_acc[6] / ((float)Ta * 360.0f);
}

// ---------------- launch ----------------
extern "C" void kernel_launch(void* const* d_in, const int* in_sizes, int n_in,
                              void* d_out, int out_size) {
    const float* hid    = (const float*)d_in[0];
    const float* aprob  = (const float*)d_in[1];
    const int* stems    = (const int*)d_in[2];
    const int* postags  = (const int*)d_in[3];
    const int* morphs   = (const int*)d_in[4];
    const int* hsel     = (const int*)d_in[5];
    const int* tsel     = (const int*)d_in[6];
    const int* asel     = (const int*)d_in[7];
    const float* stem_emb  = (const float*)d_in[8];
    const float* stem_W    = (const float*)d_in[9];
    const float* stem_b    = (const float*)d_in[10];
    const float* stem_g    = (const float*)d_in[11];
    const float* stem_beta = (const float*)d_in[12];
    const float* stem_bias = (const float*)d_in[13];
    const float* pos_emb   = (const float*)d_in[14];
    const float* pos_W     = (const float*)d_in[15];
    const float* pos_b     = (const float*)d_in[16];
    const float* pos_g     = (const float*)d_in[17];
    const float* pos_beta  = (const float*)d_in[18];
    const float* pos_bias  = (const float*)d_in[19];
    const float* morph_emb = (const float*)d_in[20];
    const float* morph_W   = (const float*)d_in[21];
    const float* morph_b   = (const float*)d_in[22];
    const float* morph_g   = (const float*)d_in[23];
    const float* morph_beta= (const float*)d_in[24];
    const float* morph_bias= (const float*)d_in[25];
    const float* aff_emb   = (const float*)d_in[26];
    const float* aff_W     = (const float*)d_in[27];
    const float* aff_b     = (const float*)d_in[28];
    const float* aff_g     = (const float*)d_in[29];
    const float* aff_beta  = (const float*)d_in[30];
    const float* aff_bias  = (const float*)d_in[31];
    float* out = (float*)d_out;

    int T  = in_sizes[5];
    int Ta = in_sizes[7];
    int mT128 = (T + 127) / 128;
    int mTa = (Ta + 63) / 64;

    __nv_bfloat16* dEb;
    __nv_bfloat16* dHb;
    cudaGetSymbolAddress((void**)&dEb, g_Eb);
    cudaGetSymbolAddress((void**)&dHb, g_Hb);

    cudaFuncSetAttribute(gemm_nt_stats_bf16,
                         cudaFuncAttributeMaxDynamicSharedMemorySize, SMEM_STATS);

    gather_x_k<<<T, 192>>>(hid, hsel);
    cvt_w_all_k<<<(HTOT * DMODEL + 255) / 256, 256>>>(stem_W, stem_b, pos_W, pos_b,
                                                      morph_W, morph_b, aff_W, aff_b);
    cvt_bf16_k<<<(50000 * 256 / 4 + 255) / 256, 256>>>(stem_emb, dEb, 50000 * 256);

    gemm_tc_gelu<<<dim3(HTOT / 128, mT128), 256>>>(T);
    ln_all_k<<<(4 * T + 7) / 8, 256>>>(stem_g, stem_beta, pos_g, pos_beta,
                                       morph_g, morph_beta, aff_g, aff_beta, T);

    // ---- stem head: Dh=256, V=50000 ----
    {
        const int Dh = 256, V = 50000, nvb = (V + 127) / 128;
        gemm_nt_stats_bf16<<<dim3(nvb, mT128), 256, SMEM_STATS>>>(dHb + 0, HTOT, stem_bias, T, V, Dh, 0);
        reduce_softmax_k<<<T, 128>>>(stem_bias, stems, tsel, V, Dh, 0, 0, 0);
    }
    // ---- pos head: Dh=128, V=200 ----
    {
        const int Dh = 128, V = 200, nvb = (V + 127) / 128;
        cvt_bf16_k<<<(V * Dh / 4 + 255) / 256, 256>>>(pos_emb, dEb, V * Dh);
        gemm_nt_stats_bf16<<<dim3(nvb, mT128), 256, SMEM_STATS>>>(dHb + 256, HTOT, pos_bias, T, V, Dh, 1);
        reduce_softmax_k<<<T, 128>>>(pos_bias, postags, tsel, V, Dh, 256, 1, 2);
    }
    // ---- morph head: Dh=128, V=400 ----
    {
        const int Dh = 128, V = 400, nvb = (V + 127) / 128;
        cvt_bf16_k<<<(V * Dh / 4 + 255) / 256, 256>>>(morph_emb, dEb, V * Dh);
        gemm_nt_stats_bf16<<<dim3(nvb, mT128), 256, SMEM_STATS>>>(dHb + 384, HTOT, morph_bias, T, V, Dh, 2);
        reduce_softmax_k<<<T, 128>>>(morph_bias, morphs, tsel, V, Dh, 384, 2, 4);
    }
    // ---- affix head: Dh=128, V=360, rows = H[asel[i]], BCE ----
    {
        const int Dh = 128, V = 360;
        gemm_nt_bce_k<<<dim3((V + 63) / 64, mTa), 256>>>(aff_emb, aff_bias, aprob, tsel, asel,
                                                         Ta, V, Dh, 512);
    }

    finalize_k<<<1, 32>>>(out, T, Ta);
}

// round 12
// speedup vs baseline: 1.4393x; 1.0405x over previous
#include <cuda_runtime.h>
#include <cuda_bf16.h>
#include <math.h>
#include <stdint.h>
#include <stddef.h>

// ---------------- problem constants ----------------
#define NSEQ 8
#define SSEQ 448
#define DMODEL 768
#define MAXT 3584          // >= N*(S-1) = 3576
#define MAXV 50000
#define HTOT 640           // 256 + 128 + 128 + 128 concatenated head dims
#define ESCALE 16.0f       // emb quantization scale (values ~0.02 -> ~0.32)
#define EINV   0.0625f

// ---------------- device scratch (no allocs allowed) ----------------
__device__ __nv_bfloat16 g_Xb[MAXT * DMODEL];        // gathered predictor states bf16
__device__ __nv_bfloat16 g_Wb[HTOT * DMODEL];        // W^T concat bf16: [n=640][k=768]
__device__ float g_bc[HTOT];                         // concatenated transform biases
__device__ float g_H[MAXT * HTOT];                   // transform output fp32 (post-gelu/LN)
__device__ uint8_t g_H8[MAXT * HTOT];                // e4m3 copy of H (post-LN), scale 1
__device__ uint8_t g_E8[MAXV * 256];                 // e4m3 copy of current head's emb, x16
__device__ float g_se[4 * MAXT];                     // per-head per-row sum(exp(z))
__device__ float g_sl[4 * MAXT];                     // per-head per-row sum(z)
__device__ float g_acc[16];                          // loss accumulators

// ---------------- asm helpers ----------------
#define CP_ASYNC16(dst, src) \
    asm volatile("cp.async.cg.shared.global [%0], [%1], 16;\n" :: "r"(dst), "l"(src))
#define CP_COMMIT() asm volatile("cp.async.commit_group;\n" ::)
#define CP_WAIT1()  asm volatile("cp.async.wait_group 1;\n" ::)
#define CP_WAIT2()  asm volatile("cp.async.wait_group 2;\n" ::)

__device__ __forceinline__ void ldsm_x4(uint32_t* r, uint32_t addr) {
    asm volatile("ldmatrix.sync.aligned.m8n8.x4.shared.b16 {%0,%1,%2,%3}, [%4];"
                 : "=r"(r[0]), "=r"(r[1]), "=r"(r[2]), "=r"(r[3]) : "r"(addr));
}

__device__ __forceinline__ void mma_bf16(float* c, const uint32_t* a, const uint32_t* b) {
    asm volatile("mma.sync.aligned.m16n8k16.row.col.f32.bf16.bf16.f32 "
                 "{%0,%1,%2,%3}, {%4,%5,%6,%7}, {%8,%9}, {%0,%1,%2,%3};\n"
                 : "+f"(c[0]), "+f"(c[1]), "+f"(c[2]), "+f"(c[3])
                 : "r"(a[0]), "r"(a[1]), "r"(a[2]), "r"(a[3]), "r"(b[0]), "r"(b[1]));
}

// FP8 e4m3 MMA: m16n8k32, fragments = m16n8k16-bf16 layout over u16 (=2 fp8) units
__device__ __forceinline__ void mma_e4m3(float* c, const uint32_t* a, const uint32_t* b) {
    asm volatile("mma.sync.aligned.m16n8k32.row.col.f32.e4m3.e4m3.f32 "
                 "{%0,%1,%2,%3}, {%4,%5,%6,%7}, {%8,%9}, {%0,%1,%2,%3};\n"
                 : "+f"(c[0]), "+f"(c[1]), "+f"(c[2]), "+f"(c[3])
                 : "r"(a[0]), "r"(a[1]), "r"(a[2]), "r"(a[3]), "r"(b[0]), "r"(b[1]));
}

__device__ __forceinline__ uint16_t f2x_e4m3(float hi, float lo) {
    uint16_t p;
    asm("cvt.rn.satfinite.e4m3x2.f32 %0, %1, %2;" : "=h"(p) : "f"(hi), "f"(lo));
    return p;
}

#define BKP 40           // padded smem row stride in u16 units (80 bytes)
#define STAGE_B (128 * BKP * 2)   // 10240 bytes per operand per stage
#define NSTAGE 4
#define SMEM_STATS (NSTAGE * STAGE_B * 2 + 2 * 4 * 128 * 4 + 128 * 4)  // 86528 B

// bf16 stage loader: 128 rows x 32 bf16 cols of A and B, 4 cp.async/thread
__device__ __forceinline__ void load_tile_pair(
    const __nv_bfloat16* __restrict__ A, int lda, int Arows, int m0,
    const __nv_bfloat16* __restrict__ B, int ldb, int Brows, int n0,
    int k0, uint32_t a_st, uint32_t b_st, int tid)
{
    #pragma unroll
    for (int i = 0; i < 2; i++) {
        int idx = tid + i * 256;
        int row = idx >> 2, c16 = idx & 3;
        int gm = m0 + row; if (gm >= Arows) gm = Arows - 1;
        CP_ASYNC16(a_st + (row * BKP + c16 * 8) * 2, A + (size_t)gm * lda + k0 + c16 * 8);
        int gn = n0 + row; if (gn >= Brows) gn = Brows - 1;
        CP_ASYNC16(b_st + (row * BKP + c16 * 8) * 2, B + (size_t)gn * ldb + k0 + c16 * 8);
    }
}

// fp8 stage loader: 128 rows x 64 fp8 cols of A and B (64B/row), 4 cp.async/thread
__device__ __forceinline__ void load_tile_pair8(
    const uint8_t* __restrict__ A, int lda, int Arows, int m0,
    const uint8_t* __restrict__ B, int ldb, int Brows, int n0,
    int k0, uint32_t a_st, uint32_t b_st, int tid)
{
    #pragma unroll
    for (int i = 0; i < 2; i++) {
        int idx = tid + i * 256;
        int row = idx >> 2, c16 = idx & 3;
        int gm = m0 + row; if (gm >= Arows) gm = Arows - 1;
        CP_ASYNC16(a_st + row * 80 + c16 * 16, A + (size_t)gm * lda + k0 + c16 * 16);
        int gn = n0 + row; if (gn >= Brows) gn = Brows - 1;
        CP_ASYNC16(b_st + row * 80 + c16 * 16, B + (size_t)gn * ldb + k0 + c16 * 16);
    }
}

// ---------------- small kernels ----------------
// emb fp32 -> e4m3 x ESCALE, 8 elems/thread
__global__ void cvt_e8_k(const float* __restrict__ src, uint8_t* __restrict__ dst, int n) {
    int i = blockIdx.x * blockDim.x + threadIdx.x;
    if (i * 8 < n) {
        float4 v0 = *(const float4*)(src + i * 8);
        float4 v1 = *(const float4*)(src + i * 8 + 4);
        uint16_t p[4];
        p[0] = f2x_e4m3(v0.y * ESCALE, v0.x * ESCALE);
        p[1] = f2x_e4m3(v0.w * ESCALE, v0.z * ESCALE);
        p[2] = f2x_e4m3(v1.y * ESCALE, v1.x * ESCALE);
        p[3] = f2x_e4m3(v1.w * ESCALE, v1.z * ESCALE);
        *(uint64_t*)(dst + i * 8) = *(uint64_t*)p;
    }
}

// pack all 4 heads' W (transposed bf16) + biases + zero the accumulators, one kernel
__global__ void cvt_w_all_k(const float* __restrict__ Ws, const float* __restrict__ bs,
                            const float* __restrict__ Wp, const float* __restrict__ bp,
                            const float* __restrict__ Wm, const float* __restrict__ bm,
                            const float* __restrict__ Wa, const float* __restrict__ ba) {
    int t = blockIdx.x * blockDim.x + threadIdx.x;
    if (t < HTOT * DMODEL) {
        int n = t / DMODEL, k = t % DMODEL;
        const float* W; int Dh, off;
        if (n < 256)      { W = Ws; Dh = 256; off = 0; }
        else if (n < 384) { W = Wp; Dh = 128; off = 256; }
        else if (n < 512) { W = Wm; Dh = 128; off = 384; }
        else              { W = Wa; Dh = 128; off = 512; }
        g_Wb[(size_t)n * DMODEL + k] = __float2bfloat16_rn(W[(size_t)k * Dh + (n - off)]);
    }
    if (t < HTOT) {
        const float* b; int off;
        if (t < 256)      { b = bs; off = 0; }
        else if (t < 384) { b = bp; off = 256; }
        else if (t < 512) { b = bm; off = 384; }
        else              { b = ba; off = 512; }
        g_bc[t] = b[t - off];
    }
    if (t < 16) g_acc[t] = 0.0f;
    if (t < 4 * MAXT) { g_se[t] = 0.0f; g_sl[t] = 0.0f; }
}

__global__ void gather_x_k(const float* __restrict__ hid, const int* __restrict__ hsel) {
    int i = blockIdx.x;
    int idx = hsel[i];
    int s = idx % SSEQ;
    int n = idx / SSEQ;
    float4 v = ((const float4*)(hid + ((size_t)s * NSEQ + n) * DMODEL))[threadIdx.x];
    __nv_bfloat16 o[4] = {__float2bfloat16_rn(v.x), __float2bfloat16_rn(v.y),
                          __float2bfloat16_rn(v.z), __float2bfloat16_rn(v.w)};
    *(uint64_t*)(g_Xb + (size_t)i * DMODEL + threadIdx.x * 4) = *(uint64_t*)o;
}

// ---------------- transform GEMM (bf16 TC): g_H = gelu(Xb @ Wb^T + bc), out stride 640 ----
__global__ void __launch_bounds__(256)
gemm_tc_gelu(int M) {
    __shared__ __align__(16) __nv_bfloat16 As[2][128 * BKP];
    __shared__ __align__(16) __nv_bfloat16 Bs[2][128 * BKP];
    int m0 = blockIdx.y * 128, n0 = blockIdx.x * 128;
    int tid = threadIdx.x;
    int warp = tid >> 5, lane = tid & 31;
    int wm = warp >> 2, wn = warp & 3;
    int gr = lane >> 2, gc = lane & 3;

    uint32_t a_base = (uint32_t)__cvta_generic_to_shared(&As[0][0]);
    uint32_t b_base = (uint32_t)__cvta_generic_to_shared(&Bs[0][0]);
    const uint32_t STAGE = 128 * BKP * 2;

    float acc[4][4][4];
    #pragma unroll
    for (int mf = 0; mf < 4; mf++)
        #pragma unroll
        for (int nf = 0; nf < 4; nf++)
            #pragma unroll
            for (int q = 0; q < 4; q++) acc[mf][nf][q] = 0.0f;

    const int nc = DMODEL / 32;   // 24
    load_tile_pair(g_Xb, DMODEL, M, m0, g_Wb, DMODEL, HTOT, n0, 0, a_base, b_base, tid);
    CP_COMMIT();

    int a_row_off = wm * 64 + ((lane >> 3) & 1) * 8 + (lane & 7);
    int a_col     = (lane >> 4) * 8;
    int b_row_off = wn * 32 + ((lane >> 4) & 1) * 8 + (lane & 7);
    int b_col     = ((lane >> 3) & 1) * 8;

    for (int c = 0; c < nc; c++) {
        int cur = c & 1;
        if (c + 1 < nc)
            load_tile_pair(g_Xb, DMODEL, M, m0, g_Wb, DMODEL, HTOT, n0,
                           (c + 1) << 5, a_base + (cur ^ 1) * STAGE, b_base + (cur ^ 1) * STAGE, tid);
        CP_COMMIT();
        CP_WAIT1();
        __syncthreads();
        uint32_t abase_s = a_base + cur * STAGE;
        uint32_t bbase_s = b_base + cur * STAGE;
        #pragma unroll
        for (int ks = 0; ks < 2; ks++) {
            uint32_t af[4][4], bf[2][4];
            #pragma unroll
            for (int mf = 0; mf < 4; mf++)
                ldsm_x4(af[mf], abase_s + ((a_row_off + mf * 16) * BKP + a_col + ks * 16) * 2);
            #pragma unroll
            for (int p = 0; p < 2; p++)
                ldsm_x4(bf[p], bbase_s + ((b_row_off + p * 16) * BKP + b_col + ks * 16) * 2);
            #pragma unroll
            for (int mf = 0; mf < 4; mf++)
                #pragma unroll
                for (int nf = 0; nf < 4; nf++)
                    mma_bf16(acc[mf][nf], af[mf], &bf[nf >> 1][(nf & 1) * 2]);
        }
        __syncthreads();
    }

    #pragma unroll
    for (int mf = 0; mf < 4; mf++) {
        #pragma unroll
        for (int h = 0; h < 2; h++) {
            int grow = m0 + wm * 64 + mf * 16 + h * 8 + gr;
            if (grow < M) {
                #pragma unroll
                for (int nf = 0; nf < 4; nf++) {
                    int col = n0 + wn * 32 + nf * 8 + gc * 2;
                    float z0 = acc[mf][nf][h * 2 + 0] + g_bc[col];
                    float z1 = acc[mf][nf][h * 2 + 1] + g_bc[col + 1];
                    float y0 = 0.5f * z0 * (1.0f + erff(z0 * 0.70710678118654752f));
                    float y1 = 0.5f * z1 * (1.0f + erff(z1 * 0.70710678118654752f));
                    *(float2*)(g_H + (size_t)grow * HTOT + col) = make_float2(y0, y1);
                }
            }
        }
    }
}

// ---------------- merged LayerNorm: one warp per (row, head); writes fp32 + e4m3 ----------
__global__ void ln_all_k(const float* __restrict__ gs, const float* __restrict__ bts,
                         const float* __restrict__ gp, const float* __restrict__ btp,
                         const float* __restrict__ gm, const float* __restrict__ btm,
                         const float* __restrict__ ga, const float* __restrict__ bta,
                         int T) {
    int w = threadIdx.x >> 5, lane = threadIdx.x & 31;
    int task = blockIdx.x * 8 + w;
    if (task >= 4 * T) return;
    int head = task / T;
    int row = task - head * T;
    int hoff, DH;
    const float* g; const float* bt;
    if (head == 0)      { hoff = 0;   DH = 256; g = gs; bt = bts; }
    else if (head == 1) { hoff = 256; DH = 128; g = gp; bt = btp; }
    else if (head == 2) { hoff = 384; DH = 128; g = gm; bt = btm; }
    else                { hoff = 512; DH = 128; g = ga; bt = bta; }
    int E = DH >> 5;
    float* base = g_H + (size_t)row * HTOT + hoff;
    float v[8];
    float s = 0.f;
    for (int i = 0; i < E; i++) { v[i] = base[lane + i * 32]; s += v[i]; }
    #pragma unroll
    for (int o = 16; o > 0; o >>= 1) s += __shfl_xor_sync(0xffffffffu, s, o);
    float mean = s / (float)DH;
    float q = 0.f;
    for (int i = 0; i < E; i++) { float d = v[i] - mean; q += d * d; }
    #pragma unroll
    for (int o = 16; o > 0; o >>= 1) q += __shfl_xor_sync(0xffffffffu, q, o);
    float r = rsqrtf(q / (float)DH + 1e-12f);
    for (int i = 0; i < E; i++) {
        float y = (v[i] - mean) * r * g[lane + i * 32] + bt[lane + i * 32];
        base[lane + i * 32] = y;
        g_H8[(size_t)row * HTOT + hoff + lane + i * 32] = (uint8_t)f2x_e4m3(0.f, y);
    }
}

// ---------------- stats GEMM (e4m3 TC, 4-stage cp.async, 2 CTA/SM, dynamic smem) ----------
// z[i,v] = (H8[i,:] . E8[v,:]) / ESCALE + bias[v]; atomicAdd sum(exp z), sum(z) per row.
// chunk = 64 fp8 per K step (2 x mma k32); fragments via b16 ldmatrix over fp8 pairs.
__global__ void __launch_bounds__(256, 2)
gemm_nt_stats_fp8(const uint8_t* __restrict__ A, int lda,
                  const float* __restrict__ vbias, int M, int V, int K, int head) {
    extern __shared__ __align__(16) char dyn[];
    float* s_s   = (float*)(dyn + NSTAGE * STAGE_B * 2);
    float* s_l   = s_s + 4 * 128;
    float* s_bias = s_l + 4 * 128;

    int m0 = blockIdx.y * 128, n0 = blockIdx.x * 128;
    int tid = threadIdx.x;
    int warp = tid >> 5, lane = tid & 31;
    int wm = warp >> 2, wn = warp & 3;
    int gr = lane >> 2, gc = lane & 3;

    if (tid < 128) {
        int v = n0 + tid;
        s_bias[tid] = (v < V) ? vbias[v] : 0.0f;
    }

    uint32_t a_base = (uint32_t)__cvta_generic_to_shared(dyn);
    uint32_t b_base = a_base + NSTAGE * STAGE_B;

    float acc[4][4][4];
    #pragma unroll
    for (int mf = 0; mf < 4; mf++)
        #pragma unroll
        for (int nf = 0; nf < 4; nf++)
            #pragma unroll
            for (int q = 0; q < 4; q++) acc[mf][nf][q] = 0.0f;

    int nc = K >> 6;   // chunks of 64 fp8

    #pragma unroll
    for (int s = 0; s < NSTAGE - 1; s++) {
        if (s < nc)
            load_tile_pair8(A, lda, M, m0, g_E8, K, V, n0, s << 6,
                            a_base + s * STAGE_B, b_base + s * STAGE_B, tid);
        CP_COMMIT();
    }

    int a_row_off = wm * 64 + ((lane >> 3) & 1) * 8 + (lane & 7);
    int a_col     = (lane >> 4) * 8;
    int b_row_off = wn * 32 + ((lane >> 4) & 1) * 8 + (lane & 7);
    int b_col     = ((lane >> 3) & 1) * 8;

    for (int c = 0; c < nc; c++) {
        CP_WAIT2();
        __syncthreads();
        int cur = c & (NSTAGE - 1);
        uint32_t abase_s = a_base + cur * STAGE_B;
        uint32_t bbase_s = b_base + cur * STAGE_B;
        #pragma unroll
        for (int ks = 0; ks < 2; ks++) {
            uint32_t af[4][4], bf[2][4];
            #pragma unroll
            for (int mf = 0; mf < 4; mf++)
                ldsm_x4(af[mf], abase_s + ((a_row_off + mf * 16) * BKP + a_col + ks * 16) * 2);
            #pragma unroll
            for (int p = 0; p < 2; p++)
                ldsm_x4(bf[p], bbase_s + ((b_row_off + p * 16) * BKP + b_col + ks * 16) * 2);
            #pragma unroll
            for (int mf = 0; mf < 4; mf++)
                #pragma unroll
                for (int nf = 0; nf < 4; nf++)
                    mma_e4m3(acc[mf][nf], af[mf], &bf[nf >> 1][(nf & 1) * 2]);
        }
        int nxt = c + NSTAGE - 1;
        if (nxt < nc) {
            int st = nxt & (NSTAGE - 1);
            load_tile_pair8(A, lda, M, m0, g_E8, K, V, n0, nxt << 6,
                            a_base + st * STAGE_B, b_base + st * STAGE_B, tid);
        }
        CP_COMMIT();
    }

    // epilogue: per-row sum(exp z), sum(z) over this block's 128 columns (max-free)
    __syncthreads();
    #pragma unroll
    for (int mf = 0; mf < 4; mf++) {
        #pragma unroll
        for (int h = 0; h < 2; h++) {
            int rowb = wm * 64 + mf * 16 + h * 8 + gr;
            float sloc = 0.f, slloc = 0.f;
            #pragma unroll
            for (int nf = 0; nf < 4; nf++) {
                #pragma unroll
                for (int q = 0; q < 2; q++) {
                    int colb = wn * 32 + nf * 8 + gc * 2 + q;
                    if (n0 + colb < V) {
                        float z = acc[mf][nf][h * 2 + q] * EINV + s_bias[colb];
                        sloc += __expf(z);
                        slloc += z;
                    }
                }
            }
            sloc  += __shfl_xor_sync(0xffffffffu, sloc, 1);
            sloc  += __shfl_xor_sync(0xffffffffu, sloc, 2);
            slloc += __shfl_xor_sync(0xffffffffu, slloc, 1);
            slloc += __shfl_xor_sync(0xffffffffu, slloc, 2);
            if (gc == 0) {
                s_s[wn * 128 + rowb] = sloc;
                s_l[wn * 128 + rowb] = slloc;
            }
        }
    }
    __syncthreads();
    if (tid < 128) {
        int grow = m0 + tid;
        if (grow < M) {
            float s = s_s[tid] + s_s[128 + tid] + s_s[256 + tid] + s_s[384 + tid];
            float sl = s_l[tid] + s_l[128 + tid] + s_l[256 + tid] + s_l[384 + tid];
            atomicAdd(&g_se[head * MAXT + grow], s);
            atomicAdd(&g_sl[head * MAXT + grow], sl);
        }
    }
}

// ---------------- per-row loss: logZ = log(sum exp), fp32 target logit, accumulate --------
__global__ void reduce_softmax_k(const float* __restrict__ emb, const float* __restrict__ vbias,
                                 const int* __restrict__ labels, const int* __restrict__ tsel,
                                 int V, int K, int hoff, int head, int accoff) {
    int row = blockIdx.x;
    int tid = threadIdx.x;   // 128 threads
    __shared__ float sd[128];
    int tgt = labels[tsel[row]];
    float d = 0.f;
    for (int k = tid; k < K; k += 128)
        d += g_H[(size_t)row * HTOT + hoff + k] * emb[(size_t)tgt * K + k];
    sd[tid] = d; __syncthreads();
    for (int o = 64; o > 0; o >>= 1) { if (tid < o) sd[tid] += sd[tid + o]; __syncthreads(); }
    if (tid == 0) {
        float logZ = logf(g_se[head * MAXT + row]);
        float tlogit = sd[0] + vbias[tgt];
        float nll = logZ - tlogit;
        float smooth = (float)V * logZ - g_sl[head * MAXT + row];
        atomicAdd(&g_acc[accoff], nll);
        atomicAdd(&g_acc[accoff + 1], smooth);
    }
}

// ---------------- affix head: z = H[asel]@emb^T + bias, fused BCE-with-logits sum ----------
__global__ void gemm_nt_bce_k(const float* __restrict__ emb, const float* __restrict__ vbias,
                              const float* __restrict__ aprob, const int* __restrict__ tsel,
                              const int* __restrict__ asel, int M, int V, int K, int hoff) {
    __shared__ __align__(16) float As[16][68];
    __shared__ __align__(16) float Bs[16][68];
    __shared__ float red[256];
    int m0 = blockIdx.y * 64, n0 = blockIdx.x * 64;
    int tid = threadIdx.x;
    int tx = tid & 15, ty = tid >> 4;
    int lrow = tid >> 2, lk4 = (tid & 3) * 4;
    float acc[4][4] = {};
    for (int k0 = 0; k0 < K; k0 += 16) {
        float4 av = make_float4(0.f, 0.f, 0.f, 0.f);
        int ar = m0 + lrow;
        if (ar < M) {
            int pr = asel[ar];
            av = *(const float4*)(g_H + (size_t)pr * HTOT + hoff + k0 + lk4);
        }
        As[lk4 + 0][lrow] = av.x; As[lk4 + 1][lrow] = av.y;
        As[lk4 + 2][lrow] = av.z; As[lk4 + 3][lrow] = av.w;
        float4 bv = make_float4(0.f, 0.f, 0.f, 0.f);
        int br = n0 + lrow;
        if (br < V) bv = *(const float4*)(emb + (size_t)br * K + k0 + lk4);
        Bs[lk4 + 0][lrow] = bv.x; Bs[lk4 + 1][lrow] = bv.y;
        Bs[lk4 + 2][lrow] = bv.z; Bs[lk4 + 3][lrow] = bv.w;
        __syncthreads();
        #pragma unroll
        for (int k = 0; k < 16; k++) {
            float4 a4 = *(const float4*)&As[k][ty * 4];
            float4 b4 = *(const float4*)&Bs[k][tx * 4];
            float a_[4] = {a4.x, a4.y, a4.z, a4.w};
            float b_[4] = {b4.x, b4.y, b4.z, b4.w};
            #pragma unroll
            for (int r = 0; r < 4; r++)
                #pragma unroll
                for (int c = 0; c < 4; c++) acc[r][c] += a_[r] * b_[c];
        }
        __syncthreads();
    }
    float lsum = 0.f;
    #pragma unroll
    for (int r = 0; r < 4; r++) {
        int grow = m0 + ty * 4 + r;
        if (grow < M) {
            int trow = tsel[asel[grow]];
            #pragma unroll
            for (int c = 0; c < 4; c++) {
                int v = n0 + tx * 4 + c;
                if (v < V) {
                    float z = acc[r][c] + vbias[v];
                    float t = aprob[(size_t)trow * 360 + v];
                    lsum += fmaxf(z, 0.f) - z * t + log1pf(__expf(-fabsf(z)));
                }
            }
        }
    }
    red[tid] = lsum; __syncthreads();
    for (int o = 128; o > 0; o >>= 1) { if (tid < o) red[tid] += red[tid + o]; __syncthreads(); }
    if (tid == 0) atomicAdd(&g_acc[6], red[0]);
}

// ---------------- finalize: assemble the 7 output scalars ----------------
__global__ void finalize_k(float* __restrict__ out, int T, int Ta) {
    if (threadIdx.x != 0 || blockIdx.x != 0) return;
    const int Vs[3] = {50000, 200, 400};
    for (int h = 0; h < 3; h++) {
        float nll_m = g_acc[2 * h] / (float)T;
        float sm_m  = g_acc[2 * h + 1] / (float)T;
        float eps_i = 0.1f / (float)(Vs[h] - 1);
        out[h] = (1.0f - 0.1f - eps_i) * nll_m + eps_i * sm_m;
        out[4 + h] = nll_m;
    }
    out[3] = g_acc[6] / ((float)Ta * 360.0f);
}

// ---------------- launch ----------------
extern "C" void kernel_launch(void* const* d_in, const int* in_sizes, int n_in,
                              void* d_out, int out_size) {
    const float* hid    = (const float*)d_in[0];
    const float* aprob  = (const float*)d_in[1];
    const int* stems    = (const int*)d_in[2];
    const int* postags  = (const int*)d_in[3];
    const int* morphs   = (const int*)d_in[4];
    const int* hsel     = (const int*)d_in[5];
    const int* tsel     = (const int*)d_in[6];
    const int* asel     = (const int*)d_in[7];
    const float* stem_emb  = (const float*)d_in[8];
    const float* stem_W    = (const float*)d_in[9];
    const float* stem_b    = (const float*)d_in[10];
    const float* stem_g    = (const float*)d_in[11];
    const float* stem_beta = (const float*)d_in[12];
    const float* stem_bias = (const float*)d_in[13];
    const float* pos_emb   = (const float*)d_in[14];
    const float* pos_W     = (const float*)d_in[15];
    const float* pos_b     = (const float*)d_in[16];
    const float* pos_g     = (const float*)d_in[17];
    const float* pos_beta  = (const float*)d_in[18];
    const float* pos_bias  = (const float*)d_in[19];
    const float* morph_emb = (const float*)d_in[20];
    const float* morph_W   = (const float*)d_in[21];
    const float* morph_b   = (const float*)d_in[22];
    const float* morph_g   = (const float*)d_in[23];
    const float* morph_beta= (const float*)d_in[24];
    const float* morph_bias= (const float*)d_in[25];
    const float* aff_emb   = (const float*)d_in[26];
    const float* aff_W     = (const float*)d_in[27];
    const float* aff_b     = (const float*)d_in[28];
    const float* aff_g     = (const float*)d_in[29];
    const float* aff_beta  = (const float*)d_in[30];
    const float* aff_bias  = (const float*)d_in[31];
    float* out = (float*)d_out;

    int T  = in_sizes[5];
    int Ta = in_sizes[7];
    int mT128 = (T + 127) / 128;
    int mTa = (Ta + 63) / 64;

    uint8_t* dE8;
    uint8_t* dH8;
    cudaGetSymbolAddress((void**)&dE8, g_E8);
    cudaGetSymbolAddress((void**)&dH8, g_H8);

    cudaFuncSetAttribute(gemm_nt_stats_fp8,
                         cudaFuncAttributeMaxDynamicSharedMemorySize, SMEM_STATS);

    gather_x_k<<<T, 192>>>(hid, hsel);
    cvt_w_all_k<<<(HTOT * DMODEL + 255) / 256, 256>>>(stem_W, stem_b, pos_W, pos_b,
                                                      morph_W, morph_b, aff_W, aff_b);
    cvt_e8_k<<<(50000 * 256 / 8 + 255) / 256, 256>>>(stem_emb, dE8, 50000 * 256);

    gemm_tc_gelu<<<dim3(HTOT / 128, mT128), 256>>>(T);
    ln_all_k<<<(4 * T + 7) / 8, 256>>>(stem_g, stem_beta, pos_g, pos_beta,
                                       morph_g, morph_beta, aff_g, aff_beta, T);

    // ---- stem head: Dh=256, V=50000 ----
    {
        const int Dh = 256, V = 50000, nvb = (V + 127) / 128;
        gemm_nt_stats_fp8<<<dim3(nvb, mT128), 256, SMEM_STATS>>>(dH8 + 0, HTOT, stem_bias, T, V, Dh, 0);
        reduce_softmax_k<<<T, 128>>>(stem_emb, stem_bias, stems, tsel, V, Dh, 0, 0, 0);
    }
    // ---- pos head: Dh=128, V=200 ----
    {
        const int Dh = 128, V = 200, nvb = (V + 127) / 128;
        cvt_e8_k<<<(V * Dh / 8 + 255) / 256, 256>>>(pos_emb, dE8, V * Dh);
        gemm_nt_stats_fp8<<<dim3(nvb, mT128), 256, SMEM_STATS>>>(dH8 + 256, HTOT, pos_bias, T, V, Dh, 1);
        reduce_softmax_k<<<T, 128>>>(pos_emb, pos_bias, postags, tsel, V, Dh, 256, 1, 2);
    }
    // ---- morph head: Dh=128, V=400 ----
    {
        const int Dh = 128, V = 400, nvb = (V + 127) / 128;
        cvt_e8_k<<<(V * Dh / 8 + 255) / 256, 256>>>(morph_emb, dE8, V * Dh);
        gemm_nt_stats_fp8<<<dim3(nvb, mT128), 256, SMEM_STATS>>>(dH8 + 384, HTOT, morph_bias, T, V, Dh, 2);
        reduce_softmax_k<<<T, 128>>>(morph_emb, morph_bias, morphs, tsel, V, Dh, 384, 2, 4);
    }
    // ---- affix head: Dh=128, V=360, rows = H[asel[i]], BCE (fp32, exact) ----
    {
        const int Dh = 128, V = 360;
        gemm_nt_bce_k<<<dim3((V + 63) / 64, mTa), 256>>>(aff_emb, aff_bias, aprob, tsel, asel,
                                                         Ta, V, Dh, 512);
    }

    finalize_k<<<1, 32>>>(out, T, Ta);
}

// round 14
// speedup vs baseline: 1.4822x; 1.0299x over previous
#include <cuda_runtime.h>
#include <cuda_bf16.h>
#include <math.h>
#include <stdint.h>
#include <stddef.h>

// ---------------- problem constants ----------------
#define NSEQ 8
#define SSEQ 448
#define DMODEL 768
#define MAXT 3584          // >= N*(S-1) = 3576
#define MAXV 50000
#define HTOT 640           // 256 + 128 + 128 + 128 concatenated head dims
#define ESCALE 16.0f       // emb quantization scale
#define EINV   0.0625f

// ---------------- device scratch (no allocs allowed) ----------------
__device__ __nv_bfloat16 g_Xb[MAXT * DMODEL];        // gathered predictor states bf16
__device__ __nv_bfloat16 g_Wb[HTOT * DMODEL];        // W^T concat bf16: [n=640][k=768]
__device__ float g_bc[HTOT];                         // concatenated transform biases
__device__ float g_H[MAXT * HTOT];                   // transform output fp32 (post-gelu/LN)
__device__ uint8_t g_H8[MAXT * HTOT];                // e4m3 copy of H (post-LN), scale 1
__device__ uint8_t g_E8[MAXV * 256];                 // e4m3 stem emb, x16
__device__ uint8_t g_E8p[200 * 128];                 // e4m3 pos emb, x16
__device__ uint8_t g_E8m[400 * 128];                 // e4m3 morph emb, x16
__device__ float g_se[4 * MAXT];                     // per-head per-row sum(exp(z))
__device__ float g_sl[4 * MAXT];                     // per-head per-row sum(z)
__device__ float g_acc[16];                          // loss accumulators

// ---------------- asm helpers ----------------
#define CP_ASYNC16(dst, src) \
    asm volatile("cp.async.cg.shared.global [%0], [%1], 16;\n" :: "r"(dst), "l"(src))
#define CP_COMMIT() asm volatile("cp.async.commit_group;\n" ::)
#define CP_WAIT0()  asm volatile("cp.async.wait_group 0;\n" ::)
#define CP_WAIT1()  asm volatile("cp.async.wait_group 1;\n" ::)

__device__ __forceinline__ void ldsm_x4(uint32_t* r, uint32_t addr) {
    asm volatile("ldmatrix.sync.aligned.m8n8.x4.shared.b16 {%0,%1,%2,%3}, [%4];"
                 : "=r"(r[0]), "=r"(r[1]), "=r"(r[2]), "=r"(r[3]) : "r"(addr));
}

__device__ __forceinline__ void mma_bf16(float* c, const uint32_t* a, const uint32_t* b) {
    asm volatile("mma.sync.aligned.m16n8k16.row.col.f32.bf16.bf16.f32 "
                 "{%0,%1,%2,%3}, {%4,%5,%6,%7}, {%8,%9}, {%0,%1,%2,%3};\n"
                 : "+f"(c[0]), "+f"(c[1]), "+f"(c[2]), "+f"(c[3])
                 : "r"(a[0]), "r"(a[1]), "r"(a[2]), "r"(a[3]), "r"(b[0]), "r"(b[1]));
}

// FP8 e4m3 MMA: m16n8k32, fragments = m16n8k16-bf16 layout over u16 (=2 fp8) units
__device__ __forceinline__ void mma_e4m3(float* c, const uint32_t* a, const uint32_t* b) {
    asm volatile("mma.sync.aligned.m16n8k32.row.col.f32.e4m3.e4m3.f32 "
                 "{%0,%1,%2,%3}, {%4,%5,%6,%7}, {%8,%9}, {%0,%1,%2,%3};\n"
                 : "+f"(c[0]), "+f"(c[1]), "+f"(c[2]), "+f"(c[3])
                 : "r"(a[0]), "r"(a[1]), "r"(a[2]), "r"(a[3]), "r"(b[0]), "r"(b[1]));
}

__device__ __forceinline__ uint16_t f2x_e4m3(float hi, float lo) {
    uint16_t p;
    asm("cvt.rn.satfinite.e4m3x2.f32 %0, %1, %2;" : "=h"(p) : "f"(hi), "f"(lo));
    return p;
}

// ---- transform GEMM (bf16) staging ----
#define BKP 40                    // bf16 row stride (80 B)
#define STAGE_B (128 * BKP * 2)   // 10240 B

// ---- stats GEMM (fp8) staging: K-chunk = 128 fp8, row stride 144 B (9x16B, odd -> no conflicts)
#define RST8 144
#define RST8U 72                  // u16 units
#define STAGE8 (128 * RST8)       // 18432 B
#define SMEM_STATS8 (2 * STAGE8 * 2 + 2 * 4 * 128 * 4 + 128 * 4)  // 78336 B

// bf16 stage loader
__device__ __forceinline__ void load_tile_pair(
    const __nv_bfloat16* __restrict__ A, int lda, int Arows, int m0,
    const __nv_bfloat16* __restrict__ B, int ldb, int Brows, int n0,
    int k0, uint32_t a_st, uint32_t b_st, int tid)
{
    #pragma unroll
    for (int i = 0; i < 2; i++) {
        int idx = tid + i * 256;
        int row = idx >> 2, c16 = idx & 3;
        int gm = m0 + row; if (gm >= Arows) gm = Arows - 1;
        CP_ASYNC16(a_st + (row * BKP + c16 * 8) * 2, A + (size_t)gm * lda + k0 + c16 * 8);
        int gn = n0 + row; if (gn >= Brows) gn = Brows - 1;
        CP_ASYNC16(b_st + (row * BKP + c16 * 8) * 2, B + (size_t)gn * ldb + k0 + c16 * 8);
    }
}

// fp8 chunk loader: 128 rows x 128 fp8 of A and B; 8 cp.async/thread
__device__ __forceinline__ void load_chunk8(
    const uint8_t* __restrict__ A, int lda, int Arows, int m0,
    const uint8_t* __restrict__ B, int ldb, int Brows, int n0,
    int k0, uint32_t a_st, uint32_t b_st, int tid)
{
    #pragma unroll
    for (int i = 0; i < 4; i++) {
        int idx = tid + i * 256;
        int row = idx >> 3, c = idx & 7;
        int gm = m0 + row; if (gm >= Arows) gm = Arows - 1;
        CP_ASYNC16(a_st + row * RST8 + c * 16, A + (size_t)gm * lda + k0 + c * 16);
        int gn = n0 + row; if (gn >= Brows) gn = Brows - 1;
        CP_ASYNC16(b_st + row * RST8 + c * 16, B + (size_t)gn * ldb + k0 + c * 16);
    }
}

// ---------------- small kernels ----------------
__global__ void cvt_e8_k(const float* __restrict__ src, uint8_t* __restrict__ dst, int n) {
    int i = blockIdx.x * blockDim.x + threadIdx.x;
    if (i * 8 < n) {
        float4 v0 = *(const float4*)(src + i * 8);
        float4 v1 = *(const float4*)(src + i * 8 + 4);
        uint16_t p[4];
        p[0] = f2x_e4m3(v0.y * ESCALE, v0.x * ESCALE);
        p[1] = f2x_e4m3(v0.w * ESCALE, v0.z * ESCALE);
        p[2] = f2x_e4m3(v1.y * ESCALE, v1.x * ESCALE);
        p[3] = f2x_e4m3(v1.w * ESCALE, v1.z * ESCALE);
        *(uint64_t*)(dst + i * 8) = *(uint64_t*)p;
    }
}

__global__ void cvt_w_all_k(const float* __restrict__ Ws, const float* __restrict__ bs,
                            const float* __restrict__ Wp, const float* __restrict__ bp,
                            const float* __restrict__ Wm, const float* __restrict__ bm,
                            const float* __restrict__ Wa, const float* __restrict__ ba) {
    int t = blockIdx.x * blockDim.x + threadIdx.x;
    if (t < HTOT * DMODEL) {
        int n = t / DMODEL, k = t % DMODEL;
        const float* W; int Dh, off;
        if (n < 256)      { W = Ws; Dh = 256; off = 0; }
        else if (n < 384) { W = Wp; Dh = 128; off = 256; }
        else if (n < 512) { W = Wm; Dh = 128; off = 384; }
        else              { W = Wa; Dh = 128; off = 512; }
        g_Wb[(size_t)n * DMODEL + k] = __float2bfloat16_rn(W[(size_t)k * Dh + (n - off)]);
    }
    if (t < HTOT) {
        const float* b; int off;
        if (t < 256)      { b = bs; off = 0; }
        else if (t < 384) { b = bp; off = 256; }
        else if (t < 512) { b = bm; off = 384; }
        else              { b = ba; off = 512; }
        g_bc[t] = b[t - off];
    }
    if (t < 16) g_acc[t] = 0.0f;
    if (t < 4 * MAXT) { g_se[t] = 0.0f; g_sl[t] = 0.0f; }
}

__global__ void gather_x_k(const float* __restrict__ hid, const int* __restrict__ hsel) {
    int i = blockIdx.x;
    int idx = hsel[i];
    int s = idx % SSEQ;
    int n = idx / SSEQ;
    float4 v = ((const float4*)(hid + ((size_t)s * NSEQ + n) * DMODEL))[threadIdx.x];
    __nv_bfloat16 o[4] = {__float2bfloat16_rn(v.x), __float2bfloat16_rn(v.y),
                          __float2bfloat16_rn(v.z), __float2bfloat16_rn(v.w)};
    *(uint64_t*)(g_Xb + (size_t)i * DMODEL + threadIdx.x * 4) = *(uint64_t*)o;
}

// ---------------- transform GEMM (bf16 TC): g_H = gelu(Xb @ Wb^T + bc), out stride 640 ----
__global__ void __launch_bounds__(256)
gemm_tc_gelu(int M) {
    __shared__ __align__(16) __nv_bfloat16 As[2][128 * BKP];
    __shared__ __align__(16) __nv_bfloat16 Bs[2][128 * BKP];
    int m0 = blockIdx.y * 128, n0 = blockIdx.x * 128;
    int tid = threadIdx.x;
    int warp = tid >> 5, lane = tid & 31;
    int wm = warp >> 2, wn = warp & 3;
    int gr = lane >> 2, gc = lane & 3;

    uint32_t a_base = (uint32_t)__cvta_generic_to_shared(&As[0][0]);
    uint32_t b_base = (uint32_t)__cvta_generic_to_shared(&Bs[0][0]);
    const uint32_t STAGE = 128 * BKP * 2;

    float acc[4][4][4];
    #pragma unroll
    for (int mf = 0; mf < 4; mf++)
        #pragma unroll
        for (int nf = 0; nf < 4; nf++)
            #pragma unroll
            for (int q = 0; q < 4; q++) acc[mf][nf][q] = 0.0f;

    const int nc = DMODEL / 32;   // 24
    load_tile_pair(g_Xb, DMODEL, M, m0, g_Wb, DMODEL, HTOT, n0, 0, a_base, b_base, tid);
    CP_COMMIT();

    int a_row_off = wm * 64 + ((lane >> 3) & 1) * 8 + (lane & 7);
    int a_col     = (lane >> 4) * 8;
    int b_row_off = wn * 32 + ((lane >> 4) & 1) * 8 + (lane & 7);
    int b_col     = ((lane >> 3) & 1) * 8;

    for (int c = 0; c < nc; c++) {
        int cur = c & 1;
        if (c + 1 < nc)
            load_tile_pair(g_Xb, DMODEL, M, m0, g_Wb, DMODEL, HTOT, n0,
                           (c + 1) << 5, a_base + (cur ^ 1) * STAGE, b_base + (cur ^ 1) * STAGE, tid);
        CP_COMMIT();
        CP_WAIT1();
        __syncthreads();
        uint32_t abase_s = a_base + cur * STAGE;
        uint32_t bbase_s = b_base + cur * STAGE;
        #pragma unroll
        for (int ks = 0; ks < 2; ks++) {
            uint32_t af[4][4], bf[2][4];
            #pragma unroll
            for (int mf = 0; mf < 4; mf++)
                ldsm_x4(af[mf], abase_s + ((a_row_off + mf * 16) * BKP + a_col + ks * 16) * 2);
            #pragma unroll
            for (int p = 0; p < 2; p++)
                ldsm_x4(bf[p], bbase_s + ((b_row_off + p * 16) * BKP + b_col + ks * 16) * 2);
            #pragma unroll
            for (int mf = 0; mf < 4; mf++)
                #pragma unroll
                for (int nf = 0; nf < 4; nf++)
                    mma_bf16(acc[mf][nf], af[mf], &bf[nf >> 1][(nf & 1) * 2]);
        }
        __syncthreads();
    }

    #pragma unroll
    for (int mf = 0; mf < 4; mf++) {
        #pragma unroll
        for (int h = 0; h < 2; h++) {
            int grow = m0 + wm * 64 + mf * 16 + h * 8 + gr;
            if (grow < M) {
                #pragma unroll
                for (int nf = 0; nf < 4; nf++) {
                    int col = n0 + wn * 32 + nf * 8 + gc * 2;
                    float z0 = acc[mf][nf][h * 2 + 0] + g_bc[col];
                    float z1 = acc[mf][nf][h * 2 + 1] + g_bc[col + 1];
                    float y0 = 0.5f * z0 * (1.0f + erff(z0 * 0.70710678118654752f));
                    float y1 = 0.5f * z1 * (1.0f + erff(z1 * 0.70710678118654752f));
                    *(float2*)(g_H + (size_t)grow * HTOT + col) = make_float2(y0, y1);
                }
            }
        }
    }
}

// ---------------- merged LayerNorm: one warp per (row, head); writes fp32 + e4m3 ----------
__global__ void ln_all_k(const float* __restrict__ gs, const float* __restrict__ bts,
                         const float* __restrict__ gp, const float* __restrict__ btp,
                         const float* __restrict__ gm, const float* __restrict__ btm,
                         const float* __restrict__ ga, const float* __restrict__ bta,
                         int T) {
    int w = threadIdx.x >> 5, lane = threadIdx.x & 31;
    int task = blockIdx.x * 8 + w;
    if (task >= 4 * T) return;
    int head = task / T;
    int row = task - head * T;
    int hoff, DH;
    const float* g; const float* bt;
    if (head == 0)      { hoff = 0;   DH = 256; g = gs; bt = bts; }
    else if (head == 1) { hoff = 256; DH = 128; g = gp; bt = btp; }
    else if (head == 2) { hoff = 384; DH = 128; g = gm; bt = btm; }
    else                { hoff = 512; DH = 128; g = ga; bt = bta; }
    int E = DH >> 5;
    float* base = g_H + (size_t)row * HTOT + hoff;
    float v[8];
    float s = 0.f;
    for (int i = 0; i < E; i++) { v[i] = base[lane + i * 32]; s += v[i]; }
    #pragma unroll
    for (int o = 16; o > 0; o >>= 1) s += __shfl_xor_sync(0xffffffffu, s, o);
    float mean = s / (float)DH;
    float q = 0.f;
    for (int i = 0; i < E; i++) { float d = v[i] - mean; q += d * d; }
    #pragma unroll
    for (int o = 16; o > 0; o >>= 1) q += __shfl_xor_sync(0xffffffffu, q, o);
    float r = rsqrtf(q / (float)DH + 1e-12f);
    for (int i = 0; i < E; i++) {
        float y = (v[i] - mean) * r * g[lane + i * 32] + bt[lane + i * 32];
        base[lane + i * 32] = y;
        g_H8[(size_t)row * HTOT + hoff + lane + i * 32] = (uint8_t)f2x_e4m3(0.f, y);
    }
}

// ---------------- stats GEMM (e4m3, K-chunks of 128, minimal barriers, 2 CTA/SM) ----------
// z[i,v] = (H8 . E8)/ESCALE + bias; atomicAdd sum(exp z), sum(z).  nc = K/128 (2 or 1).
__global__ void __launch_bounds__(256, 2)
gemm_nt_stats_fp8(const uint8_t* __restrict__ A, int lda, const uint8_t* __restrict__ E,
                  const float* __restrict__ vbias, int M, int V, int K, int head) {
    extern __shared__ __align__(16) char dyn[];
    float* s_s   = (float*)(dyn + 2 * STAGE8 * 2);
    float* s_l   = s_s + 4 * 128;
    float* s_bias = s_l + 4 * 128;

    int m0 = blockIdx.y * 128, n0 = blockIdx.x * 128;
    int tid = threadIdx.x;
    int warp = tid >> 5, lane = tid & 31;
    int wm = warp >> 2, wn = warp & 3;
    int gr = lane >> 2, gc = lane & 3;

    if (tid < 128) {
        int v = n0 + tid;
        s_bias[tid] = (v < V) ? vbias[v] : 0.0f;
    }

    uint32_t a_base = (uint32_t)__cvta_generic_to_shared(dyn);
    uint32_t b_base = a_base + 2 * STAGE8;

    float acc[4][4][4];
    #pragma unroll
    for (int mf = 0; mf < 4; mf++)
        #pragma unroll
        for (int nf = 0; nf < 4; nf++)
            #pragma unroll
            for (int q = 0; q < 4; q++) acc[mf][nf][q] = 0.0f;

    int nc = K >> 7;   // chunks of 128 fp8 (2 for stem, 1 for Dh=128)

    load_chunk8(A, lda, M, m0, E, K, V, n0, 0, a_base, b_base, tid);
    CP_COMMIT();

    int a_row_off = wm * 64 + ((lane >> 3) & 1) * 8 + (lane & 7);
    int a_col     = (lane >> 4) * 8;
    int b_row_off = wn * 32 + ((lane >> 4) & 1) * 8 + (lane & 7);
    int b_col     = ((lane >> 3) & 1) * 8;

    for (int c = 0; c < nc; c++) {
        if (c + 1 < nc) {
            load_chunk8(A, lda, M, m0, E, K, V, n0, (c + 1) << 7,
                        a_base + ((c + 1) & 1) * STAGE8, b_base + ((c + 1) & 1) * STAGE8, tid);
            CP_COMMIT();
            CP_WAIT1();
        } else {
            CP_WAIT0();
        }
        __syncthreads();
        uint32_t abase_s = a_base + (c & 1) * STAGE8;
        uint32_t bbase_s = b_base + (c & 1) * STAGE8;
        #pragma unroll
        for (int ks = 0; ks < 4; ks++) {
            uint32_t af[4][4], bf[2][4];
            #pragma unroll
            for (int mf = 0; mf < 4; mf++)
                ldsm_x4(af[mf], abase_s + ((a_row_off + mf * 16) * RST8U + a_col + ks * 16) * 2);
            #pragma unroll
            for (int p = 0; p < 2; p++)
                ldsm_x4(bf[p], bbase_s + ((b_row_off + p * 16) * RST8U + b_col + ks * 16) * 2);
            #pragma unroll
            for (int mf = 0; mf < 4; mf++)
                #pragma unroll
                for (int nf = 0; nf < 4; nf++)
                    mma_e4m3(acc[mf][nf], af[mf], &bf[nf >> 1][(nf & 1) * 2]);
        }
        // stages are never reused (nc <= 2 == #stages): no trailing barrier
    }

    // epilogue: per-row sum(exp z), sum(z) over this block's 128 columns (max-free)
    __syncthreads();
    #pragma unroll
    for (int mf = 0; mf < 4; mf++) {
        #pragma unroll
        for (int h = 0; h < 2; h++) {
            int rowb = wm * 64 + mf * 16 + h * 8 + gr;
            float sloc = 0.f, slloc = 0.f;
            #pragma unroll
            for (int nf = 0; nf < 4; nf++) {
                #pragma unroll
                for (int q = 0; q < 2; q++) {
                    int colb = wn * 32 + nf * 8 + gc * 2 + q;
                    if (n0 + colb < V) {
                        float z = acc[mf][nf][h * 2 + q] * EINV + s_bias[colb];
                        sloc += __expf(z);
                        slloc += z;
                    }
                }
            }
            sloc  += __shfl_xor_sync(0xffffffffu, sloc, 1);
            sloc  += __shfl_xor_sync(0xffffffffu, sloc, 2);
            slloc += __shfl_xor_sync(0xffffffffu, slloc, 1);
            slloc += __shfl_xor_sync(0xffffffffu, slloc, 2);
            if (gc == 0) {
                s_s[wn * 128 + rowb] = sloc;
                s_l[wn * 128 + rowb] = slloc;
            }
        }
    }
    __syncthreads();
    if (tid < 128) {
        int grow = m0 + tid;
        if (grow < M) {
            float s = s_s[tid] + s_s[128 + tid] + s_s[256 + tid] + s_s[384 + tid];
            float sl = s_l[tid] + s_l[128 + tid] + s_l[256 + tid] + s_l[384 + tid];
            atomicAdd(&g_se[head * MAXT + grow], s);
            atomicAdd(&g_sl[head * MAXT + grow], sl);
        }
    }
}

// ---------------- per-row loss: logZ = log(sum exp), fp32 target logit, accumulate --------
__global__ void reduce_softmax_k(const float* __restrict__ emb, const float* __restrict__ vbias,
                                 const int* __restrict__ labels, const int* __restrict__ tsel,
                                 int V, int K, int hoff, int head, int accoff) {
    int row = blockIdx.x;
    int tid = threadIdx.x;   // 128 threads
    __shared__ float sd[128];
    int tgt = labels[tsel[row]];
    float d = 0.f;
    for (int k = tid; k < K; k += 128)
        d += g_H[(size_t)row * HTOT + hoff + k] * emb[(size_t)tgt * K + k];
    sd[tid] = d; __syncthreads();
    for (int o = 64; o > 0; o >>= 1) { if (tid < o) sd[tid] += sd[tid + o]; __syncthreads(); }
    if (tid == 0) {
        float logZ = logf(g_se[head * MAXT + row]);
        float tlogit = sd[0] + vbias[tgt];
        float nll = logZ - tlogit;
        float smooth = (float)V * logZ - g_sl[head * MAXT + row];
        atomicAdd(&g_acc[accoff], nll);
        atomicAdd(&g_acc[accoff + 1], smooth);
    }
}

// ---------------- affix head: z = H[asel]@emb^T + bias, fused BCE-with-logits sum ----------
__global__ void gemm_nt_bce_k(const float* __restrict__ emb, const float* __restrict__ vbias,
                              const float* __restrict__ aprob, const int* __restrict__ tsel,
                              const int* __restrict__ asel, int M, int V, int K, int hoff) {
    __shared__ __align__(16) float As[16][68];
    __shared__ __align__(16) float Bs[16][68];
    __shared__ float red[256];
    int m0 = blockIdx.y * 64, n0 = blockIdx.x * 64;
    int tid = threadIdx.x;
    int tx = tid & 15, ty = tid >> 4;
    int lrow = tid >> 2, lk4 = (tid & 3) * 4;
    float acc[4][4] = {};
    for (int k0 = 0; k0 < K; k0 += 16) {
        float4 av = make_float4(0.f, 0.f, 0.f, 0.f);
        int ar = m0 + lrow;
        if (ar < M) {
            int pr = asel[ar];
            av = *(const float4*)(g_H + (size_t)pr * HTOT + hoff + k0 + lk4);
        }
        As[lk4 + 0][lrow] = av.x; As[lk4 + 1][lrow] = av.y;
        As[lk4 + 2][lrow] = av.z; As[lk4 + 3][lrow] = av.w;
        float4 bv = make_float4(0.f, 0.f, 0.f, 0.f);
        int br = n0 + lrow;
        if (br < V) bv = *(const float4*)(emb + (size_t)br * K + k0 + lk4);
        Bs[lk4 + 0][lrow] = bv.x; Bs[lk4 + 1][lrow] = bv.y;
        Bs[lk4 + 2][lrow] = bv.z; Bs[lk4 + 3][lrow] = bv.w;
        __syncthreads();
        #pragma unroll
        for (int k = 0; k < 16; k++) {
            float4 a4 = *(const float4*)&As[k][ty * 4];
            float4 b4 = *(const float4*)&Bs[k][tx * 4];
            float a_[4] = {a4.x, a4.y, a4.z, a4.w};
            float b_[4] = {b4.x, b4.y, b4.z, b4.w};
            #pragma unroll
            for (int r = 0; r < 4; r++)
                #pragma unroll
                for (int c = 0; c < 4; c++) acc[r][c] += a_[r] * b_[c];
        }
        __syncthreads();
    }
    float lsum = 0.f;
    #pragma unroll
    for (int r = 0; r < 4; r++) {
        int grow = m0 + ty * 4 + r;
        if (grow < M) {
            int trow = tsel[asel[grow]];
            #pragma unroll
            for (int c = 0; c < 4; c++) {
                int v = n0 + tx * 4 + c;
                if (v < V) {
                    float z = acc[r][c] + vbias[v];
                    float t = aprob[(size_t)trow * 360 + v];
                    lsum += fmaxf(z, 0.f) - z * t + log1pf(__expf(-fabsf(z)));
                }
            }
        }
    }
    red[tid] = lsum; __syncthreads();
    for (int o = 128; o > 0; o >>= 1) { if (tid < o) red[tid] += red[tid + o]; __syncthreads(); }
    if (tid == 0) atomicAdd(&g_acc[6], red[0]);
}

// ---------------- finalize: assemble the 7 output scalars ----------------
__global__ void finalize_k(float* __restrict__ out, int T, int Ta) {
    if (threadIdx.x != 0 || blockIdx.x != 0) return;
    const int Vs[3] = {50000, 200, 400};
    for (int h = 0; h < 3; h++) {
        float nll_m = g_acc[2 * h] / (float)T;
        float sm_m  = g_acc[2 * h + 1] / (float)T;
        float eps_i = 0.1f / (float)(Vs[h] - 1);
        out[h] = (1.0f - 0.1f - eps_i) * nll_m + eps_i * sm_m;
        out[4 + h] = nll_m;
    }
    out[3] = g_acc[6] / ((float)Ta * 360.0f);
}

// ---------------- launch ----------------
extern "C" void kernel_launch(void* const* d_in, const int* in_sizes, int n_in,
                              void* d_out, int out_size) {
    const float* hid    = (const float*)d_in[0];
    const float* aprob  = (const float*)d_in[1];
    const int* stems    = (const int*)d_in[2];
    const int* postags  = (const int*)d_in[3];
    const int* morphs   = (const int*)d_in[4];
    const int* hsel     = (const int*)d_in[5];
    const int* tsel     = (const int*)d_in[6];
    const int* asel     = (const int*)d_in[7];
    const float* stem_emb  = (const float*)d_in[8];
    const float* stem_W    = (const float*)d_in[9];
    const float* stem_b    = (const float*)d_in[10];
    const float* stem_g    = (const float*)d_in[11];
    const float* stem_beta = (const float*)d_in[12];
    const float* stem_bias = (const float*)d_in[13];
    const float* pos_emb   = (const float*)d_in[14];
    const float* pos_W     = (const float*)d_in[15];
    const float* pos_b     = (const float*)d_in[16];
    const float* pos_g     = (const float*)d_in[17];
    const float* pos_beta  = (const float*)d_in[18];
    const float* pos_bias  = (const float*)d_in[19];
    const float* morph_emb = (const float*)d_in[20];
    const float* morph_W   = (const float*)d_in[21];
    const float* morph_b   = (const float*)d_in[22];
    const float* morph_g   = (const float*)d_in[23];
    const float* morph_beta= (const float*)d_in[24];
    const float* morph_bias= (const float*)d_in[25];
    const float* aff_emb   = (const float*)d_in[26];
    const float* aff_W     = (const float*)d_in[27];
    const float* aff_b     = (const float*)d_in[28];
    const float* aff_g     = (const float*)d_in[29];
    const float* aff_beta  = (const float*)d_in[30];
    const float* aff_bias  = (const float*)d_in[31];
    float* out = (float*)d_out;

    int T  = in_sizes[5];
    int Ta = in_sizes[7];
    int mT128 = (T + 127) / 128;
    int mTa = (Ta + 63) / 64;

    uint8_t *dE8, *dE8p, *dE8m, *dH8;
    cudaGetSymbolAddress((void**)&dE8, g_E8);
    cudaGetSymbolAddress((void**)&dE8p, g_E8p);
    cudaGetSymbolAddress((void**)&dE8m, g_E8m);
    cudaGetSymbolAddress((void**)&dH8, g_H8);

    cudaFuncSetAttribute(gemm_nt_stats_fp8,
                         cudaFuncAttributeMaxDynamicSharedMemorySize, SMEM_STATS8);

    gather_x_k<<<T, 192>>>(hid, hsel);
    cvt_w_all_k<<<(HTOT * DMODEL + 255) / 256, 256>>>(stem_W, stem_b, pos_W, pos_b,
                                                      morph_W, morph_b, aff_W, aff_b);
    cvt_e8_k<<<(50000 * 256 / 8 + 255) / 256, 256>>>(stem_emb, dE8, 50000 * 256);
    cvt_e8_k<<<(200 * 128 / 8 + 255) / 256, 256>>>(pos_emb, dE8p, 200 * 128);
    cvt_e8_k<<<(400 * 128 / 8 + 255) / 256, 256>>>(morph_emb, dE8m, 400 * 128);

    gemm_tc_gelu<<<dim3(HTOT / 128, mT128), 256>>>(T);
    ln_all_k<<<(4 * T + 7) / 8, 256>>>(stem_g, stem_beta, pos_g, pos_beta,
                                       morph_g, morph_beta, aff_g, aff_beta, T);

    // ---- stem head: Dh=256, V=50000 ----
    {
        const int Dh = 256, V = 50000, nvb = (V + 127) / 128;
        gemm_nt_stats_fp8<<<dim3(nvb, mT128), 256, SMEM_STATS8>>>(dH8 + 0, HTOT, dE8,
                                                                  stem_bias, T, V, Dh, 0);
        reduce_softmax_k<<<T, 128>>>(stem_emb, stem_bias, stems, tsel, V, Dh, 0, 0, 0);
    }
    // ---- pos head: Dh=128, V=200 ----
    {
        const int Dh = 128, V = 200, nvb = (V + 127) / 128;
        gemm_nt_stats_fp8<<<dim3(nvb, mT128), 256, SMEM_STATS8>>>(dH8 + 256, HTOT, dE8p,
                                                                  pos_bias, T, V, Dh, 1);
        reduce_softmax_k<<<T, 128>>>(pos_emb, pos_bias, postags, tsel, V, Dh, 256, 1, 2);
    }
    // ---- morph head: Dh=128, V=400 ----
    {
        const int Dh = 128, V = 400, nvb = (V + 127) / 128;
        gemm_nt_stats_fp8<<<dim3(nvb, mT128), 256, SMEM_STATS8>>>(dH8 + 384, HTOT, dE8m,
                                                                  morph_bias, T, V, Dh, 2);
        reduce_softmax_k<<<T, 128>>>(morph_emb, morph_bias, morphs, tsel, V, Dh, 384, 2, 4);
    }
    // ---- affix head: Dh=128, V=360, rows = H[asel[i]], BCE (fp32, exact) ----
    {
        const int Dh = 128, V = 360;
        gemm_nt_bce_k<<<dim3((V + 63) / 64, mTa), 256>>>(aff_emb, aff_bias, aprob, tsel, asel,
                                                         Ta, V, Dh, 512);
    }

    finalize_k<<<1, 32>>>(out, T, Ta);
}

// round 15
// speedup vs baseline: 1.5111x; 1.0195x over previous
#include <cuda_runtime.h>
#include <cuda_bf16.h>
#include <math.h>
#include <stdint.h>
#include <stddef.h>

// ---------------- problem constants ----------------
#define NSEQ 8
#define SSEQ 448
#define DMODEL 768
#define MAXT 3584          // >= N*(S-1) = 3576
#define MAXV 50000
#define HTOT 640           // 256 + 128 + 128 + 128 concatenated head dims
#define ESCALE 16.0f       // emb quantization scale
#define EINV   0.0625f

// ---------------- device scratch (no allocs allowed) ----------------
__device__ __nv_bfloat16 g_Xb[MAXT * DMODEL];        // gathered predictor states bf16
__device__ __nv_bfloat16 g_Wb[HTOT * DMODEL];        // W^T concat bf16: [n=640][k=768]
__device__ float g_bc[HTOT];                         // concatenated transform biases
__device__ float g_H[MAXT * HTOT];                   // transform output fp32 (post-gelu/LN)
__device__ uint8_t g_H8[MAXT * HTOT];                // e4m3 copy of H (post-LN), scale 1
__device__ uint8_t g_E8[MAXV * 256];                 // e4m3 stem emb, x16
__device__ uint8_t g_E8p[200 * 128];                 // e4m3 pos emb, x16
__device__ uint8_t g_E8m[400 * 128];                 // e4m3 morph emb, x16
__device__ float g_se[4 * MAXT];                     // per-head per-row sum(exp(z))
__device__ float g_sl[4 * MAXT];                     // per-head per-row sum(z)
__device__ float g_acc[16];                          // loss accumulators

// ---------------- asm helpers ----------------
#define CP_ASYNC16(dst, src) \
    asm volatile("cp.async.cg.shared.global [%0], [%1], 16;\n" :: "r"(dst), "l"(src))
#define CP_COMMIT() asm volatile("cp.async.commit_group;\n" ::)
#define CP_WAIT0()  asm volatile("cp.async.wait_group 0;\n" ::)
#define CP_WAIT1()  asm volatile("cp.async.wait_group 1;\n" ::)

__device__ __forceinline__ void ldsm_x4(uint32_t* r, uint32_t addr) {
    asm volatile("ldmatrix.sync.aligned.m8n8.x4.shared.b16 {%0,%1,%2,%3}, [%4];"
                 : "=r"(r[0]), "=r"(r[1]), "=r"(r[2]), "=r"(r[3]) : "r"(addr));
}

__device__ __forceinline__ void mma_bf16(float* c, const uint32_t* a, const uint32_t* b) {
    asm volatile("mma.sync.aligned.m16n8k16.row.col.f32.bf16.bf16.f32 "
                 "{%0,%1,%2,%3}, {%4,%5,%6,%7}, {%8,%9}, {%0,%1,%2,%3};\n"
                 : "+f"(c[0]), "+f"(c[1]), "+f"(c[2]), "+f"(c[3])
                 : "r"(a[0]), "r"(a[1]), "r"(a[2]), "r"(a[3]), "r"(b[0]), "r"(b[1]));
}

// FP8 e4m3 MMA: m16n8k32, fragments = m16n8k16-bf16 layout over u16 (=2 fp8) units
__device__ __forceinline__ void mma_e4m3(float* c, const uint32_t* a, const uint32_t* b) {
    asm volatile("mma.sync.aligned.m16n8k32.row.col.f32.e4m3.e4m3.f32 "
                 "{%0,%1,%2,%3}, {%4,%5,%6,%7}, {%8,%9}, {%0,%1,%2,%3};\n"
                 : "+f"(c[0]), "+f"(c[1]), "+f"(c[2]), "+f"(c[3])
                 : "r"(a[0]), "r"(a[1]), "r"(a[2]), "r"(a[3]), "r"(b[0]), "r"(b[1]));
}

__device__ __forceinline__ uint16_t f2x_e4m3(float hi, float lo) {
    uint16_t p;
    asm("cvt.rn.satfinite.e4m3x2.f32 %0, %1, %2;" : "=h"(p) : "f"(hi), "f"(lo));
    return p;
}

// ---- transform GEMM (bf16) staging ----
#define BKP 40                    // bf16 row stride (80 B)
#define STAGE_B (128 * BKP * 2)   // 10240 B

// ---- stats GEMM (fp8) staging: K-chunk = 128 fp8, row stride 144 B (9x16B, odd) ----
#define RST8 144
#define RST8U 72                  // u16 units
#define STAGE8 (128 * RST8)       // 18432 B
#define SMEM_STATS8 (2 * STAGE8 * 2 + 2 * 4 * 128 * 4 + 128 * 4)  // 78336 B

// bf16 stage loader
__device__ __forceinline__ void load_tile_pair(
    const __nv_bfloat16* __restrict__ A, int lda, int Arows, int m0,
    const __nv_bfloat16* __restrict__ B, int ldb, int Brows, int n0,
    int k0, uint32_t a_st, uint32_t b_st, int tid)
{
    #pragma unroll
    for (int i = 0; i < 2; i++) {
        int idx = tid + i * 256;
        int row = idx >> 2, c16 = idx & 3;
        int gm = m0 + row; if (gm >= Arows) gm = Arows - 1;
        CP_ASYNC16(a_st + (row * BKP + c16 * 8) * 2, A + (size_t)gm * lda + k0 + c16 * 8);
        int gn = n0 + row; if (gn >= Brows) gn = Brows - 1;
        CP_ASYNC16(b_st + (row * BKP + c16 * 8) * 2, B + (size_t)gn * ldb + k0 + c16 * 8);
    }
}

// fp8 chunk loader: 128 rows x 128 fp8 of A and B; 8 cp.async/thread
__device__ __forceinline__ void load_chunk8(
    const uint8_t* __restrict__ A, int lda, int Arows, int m0,
    const uint8_t* __restrict__ B, int ldb, int Brows, int n0,
    int k0, uint32_t a_st, uint32_t b_st, int tid)
{
    #pragma unroll
    for (int i = 0; i < 4; i++) {
        int idx = tid + i * 256;
        int row = idx >> 3, c = idx & 7;
        int gm = m0 + row; if (gm >= Arows) gm = Arows - 1;
        CP_ASYNC16(a_st + row * RST8 + c * 16, A + (size_t)gm * lda + k0 + c * 16);
        int gn = n0 + row; if (gn >= Brows) gn = Brows - 1;
        CP_ASYNC16(b_st + row * RST8 + c * 16, B + (size_t)gn * ldb + k0 + c * 16);
    }
}

// ---------------- small kernels ----------------
__device__ __forceinline__ void cvt8(const float* __restrict__ s, uint8_t* __restrict__ d) {
    float4 v0 = *(const float4*)s;
    float4 v1 = *(const float4*)(s + 4);
    uint16_t p[4];
    p[0] = f2x_e4m3(v0.y * ESCALE, v0.x * ESCALE);
    p[1] = f2x_e4m3(v0.w * ESCALE, v0.z * ESCALE);
    p[2] = f2x_e4m3(v1.y * ESCALE, v1.x * ESCALE);
    p[3] = f2x_e4m3(v1.w * ESCALE, v1.z * ESCALE);
    *(uint64_t*)d = *(uint64_t*)p;
}

// all three embedding tables -> fp8, one launch
__global__ void cvt_e8_all_k(const float* __restrict__ s, const float* __restrict__ p,
                             const float* __restrict__ m) {
    int i = blockIdx.x * blockDim.x + threadIdx.x;
    const int ns = 50000 * 256 / 8;
    const int np = 200 * 128 / 8;
    const int nm = 400 * 128 / 8;
    if (i < ns) cvt8(s + (size_t)i * 8, g_E8 + (size_t)i * 8);
    else if (i < ns + np) { int j = i - ns; cvt8(p + (size_t)j * 8, g_E8p + (size_t)j * 8); }
    else if (i < ns + np + nm) { int j = i - ns - np; cvt8(m + (size_t)j * 8, g_E8m + (size_t)j * 8); }
}

__global__ void cvt_w_all_k(const float* __restrict__ Ws, const float* __restrict__ bs,
                            const float* __restrict__ Wp, const float* __restrict__ bp,
                            const float* __restrict__ Wm, const float* __restrict__ bm,
                            const float* __restrict__ Wa, const float* __restrict__ ba) {
    int t = blockIdx.x * blockDim.x + threadIdx.x;
    if (t < HTOT * DMODEL) {
        int n = t / DMODEL, k = t % DMODEL;
        const float* W; int Dh, off;
        if (n < 256)      { W = Ws; Dh = 256; off = 0; }
        else if (n < 384) { W = Wp; Dh = 128; off = 256; }
        else if (n < 512) { W = Wm; Dh = 128; off = 384; }
        else              { W = Wa; Dh = 128; off = 512; }
        g_Wb[(size_t)n * DMODEL + k] = __float2bfloat16_rn(W[(size_t)k * Dh + (n - off)]);
    }
    if (t < HTOT) {
        const float* b; int off;
        if (t < 256)      { b = bs; off = 0; }
        else if (t < 384) { b = bp; off = 256; }
        else if (t < 512) { b = bm; off = 384; }
        else              { b = ba; off = 512; }
        g_bc[t] = b[t - off];
    }
    if (t < 16) g_acc[t] = 0.0f;
    if (t < 4 * MAXT) { g_se[t] = 0.0f; g_sl[t] = 0.0f; }
}

__global__ void gather_x_k(const float* __restrict__ hid, const int* __restrict__ hsel) {
    int i = blockIdx.x;
    int idx = hsel[i];
    int s = idx % SSEQ;
    int n = idx / SSEQ;
    float4 v = ((const float4*)(hid + ((size_t)s * NSEQ + n) * DMODEL))[threadIdx.x];
    __nv_bfloat16 o[4] = {__float2bfloat16_rn(v.x), __float2bfloat16_rn(v.y),
                          __float2bfloat16_rn(v.z), __float2bfloat16_rn(v.w)};
    *(uint64_t*)(g_Xb + (size_t)i * DMODEL + threadIdx.x * 4) = *(uint64_t*)o;
}

// ---------------- transform GEMM (bf16 TC): g_H = gelu(Xb @ Wb^T + bc), out stride 640 ----
__global__ void __launch_bounds__(256)
gemm_tc_gelu(int M) {
    __shared__ __align__(16) __nv_bfloat16 As[2][128 * BKP];
    __shared__ __align__(16) __nv_bfloat16 Bs[2][128 * BKP];
    int m0 = blockIdx.y * 128, n0 = blockIdx.x * 128;
    int tid = threadIdx.x;
    int warp = tid >> 5, lane = tid & 31;
    int wm = warp >> 2, wn = warp & 3;
    int gr = lane >> 2, gc = lane & 3;

    uint32_t a_base = (uint32_t)__cvta_generic_to_shared(&As[0][0]);
    uint32_t b_base = (uint32_t)__cvta_generic_to_shared(&Bs[0][0]);
    const uint32_t STAGE = 128 * BKP * 2;

    float acc[4][4][4];
    #pragma unroll
    for (int mf = 0; mf < 4; mf++)
        #pragma unroll
        for (int nf = 0; nf < 4; nf++)
            #pragma unroll
            for (int q = 0; q < 4; q++) acc[mf][nf][q] = 0.0f;

    const int nc = DMODEL / 32;   // 24
    load_tile_pair(g_Xb, DMODEL, M, m0, g_Wb, DMODEL, HTOT, n0, 0, a_base, b_base, tid);
    CP_COMMIT();

    int a_row_off = wm * 64 + ((lane >> 3) & 1) * 8 + (lane & 7);
    int a_col     = (lane >> 4) * 8;
    int b_row_off = wn * 32 + ((lane >> 4) & 1) * 8 + (lane & 7);
    int b_col     = ((lane >> 3) & 1) * 8;

    for (int c = 0; c < nc; c++) {
        int cur = c & 1;
        if (c + 1 < nc)
            load_tile_pair(g_Xb, DMODEL, M, m0, g_Wb, DMODEL, HTOT, n0,
                           (c + 1) << 5, a_base + (cur ^ 1) * STAGE, b_base + (cur ^ 1) * STAGE, tid);
        CP_COMMIT();
        CP_WAIT1();
        __syncthreads();
        uint32_t abase_s = a_base + cur * STAGE;
        uint32_t bbase_s = b_base + cur * STAGE;
        #pragma unroll
        for (int ks = 0; ks < 2; ks++) {
            uint32_t af[4][4], bf[2][4];
            #pragma unroll
            for (int mf = 0; mf < 4; mf++)
                ldsm_x4(af[mf], abase_s + ((a_row_off + mf * 16) * BKP + a_col + ks * 16) * 2);
            #pragma unroll
            for (int p = 0; p < 2; p++)
                ldsm_x4(bf[p], bbase_s + ((b_row_off + p * 16) * BKP + b_col + ks * 16) * 2);
            #pragma unroll
            for (int mf = 0; mf < 4; mf++)
                #pragma unroll
                for (int nf = 0; nf < 4; nf++)
                    mma_bf16(acc[mf][nf], af[mf], &bf[nf >> 1][(nf & 1) * 2]);
        }
        __syncthreads();
    }

    #pragma unroll
    for (int mf = 0; mf < 4; mf++) {
        #pragma unroll
        for (int h = 0; h < 2; h++) {
            int grow = m0 + wm * 64 + mf * 16 + h * 8 + gr;
            if (grow < M) {
                #pragma unroll
                for (int nf = 0; nf < 4; nf++) {
                    int col = n0 + wn * 32 + nf * 8 + gc * 2;
                    float z0 = acc[mf][nf][h * 2 + 0] + g_bc[col];
                    float z1 = acc[mf][nf][h * 2 + 1] + g_bc[col + 1];
                    float y0 = 0.5f * z0 * (1.0f + erff(z0 * 0.70710678118654752f));
                    float y1 = 0.5f * z1 * (1.0f + erff(z1 * 0.70710678118654752f));
                    *(float2*)(g_H + (size_t)grow * HTOT + col) = make_float2(y0, y1);
                }
            }
        }
    }
}

// ---------------- merged LayerNorm: one warp per (row, head); writes fp32 + e4m3 ----------
__global__ void ln_all_k(const float* __restrict__ gs, const float* __restrict__ bts,
                         const float* __restrict__ gp, const float* __restrict__ btp,
                         const float* __restrict__ gm, const float* __restrict__ btm,
                         const float* __restrict__ ga, const float* __restrict__ bta,
                         int T) {
    int w = threadIdx.x >> 5, lane = threadIdx.x & 31;
    int task = blockIdx.x * 8 + w;
    if (task >= 4 * T) return;
    int head = task / T;
    int row = task - head * T;
    int hoff, DH;
    const float* g; const float* bt;
    if (head == 0)      { hoff = 0;   DH = 256; g = gs; bt = bts; }
    else if (head == 1) { hoff = 256; DH = 128; g = gp; bt = btp; }
    else if (head == 2) { hoff = 384; DH = 128; g = gm; bt = btm; }
    else                { hoff = 512; DH = 128; g = ga; bt = bta; }
    int E = DH >> 5;
    float* base = g_H + (size_t)row * HTOT + hoff;
    float v[8];
    float s = 0.f;
    for (int i = 0; i < E; i++) { v[i] = base[lane + i * 32]; s += v[i]; }
    #pragma unroll
    for (int o = 16; o > 0; o >>= 1) s += __shfl_xor_sync(0xffffffffu, s, o);
    float mean = s / (float)DH;
    float q = 0.f;
    for (int i = 0; i < E; i++) { float d = v[i] - mean; q += d * d; }
    #pragma unroll
    for (int o = 16; o > 0; o >>= 1) q += __shfl_xor_sync(0xffffffffu, q, o);
    float r = rsqrtf(q / (float)DH + 1e-12f);
    for (int i = 0; i < E; i++) {
        float y = (v[i] - mean) * r * g[lane + i * 32] + bt[lane + i * 32];
        base[lane + i * 32] = y;
        g_H8[(size_t)row * HTOT + hoff + lane + i * 32] = (uint8_t)f2x_e4m3(0.f, y);
    }
}

// ---------------- per-block stats GEMM body (fp8, K-chunks of 128) ----------------
__device__ void stats_block(int nIdx, int mIdx,
                            const uint8_t* __restrict__ A, const uint8_t* __restrict__ E,
                            const float* __restrict__ vbias, int M, int V, int K, int head) {
    extern __shared__ __align__(16) char dyn[];
    float* s_s   = (float*)(dyn + 2 * STAGE8 * 2);
    float* s_l   = s_s + 4 * 128;
    float* s_bias = s_l + 4 * 128;

    int m0 = mIdx * 128, n0 = nIdx * 128;
    int tid = threadIdx.x;
    int warp = tid >> 5, lane = tid & 31;
    int wm = warp >> 2, wn = warp & 3;
    int gr = lane >> 2, gc = lane & 3;

    if (tid < 128) {
        int v = n0 + tid;
        s_bias[tid] = (v < V) ? vbias[v] : 0.0f;
    }

    uint32_t a_base = (uint32_t)__cvta_generic_to_shared(dyn);
    uint32_t b_base = a_base + 2 * STAGE8;

    float acc[4][4][4];
    #pragma unroll
    for (int mf = 0; mf < 4; mf++)
        #pragma unroll
        for (int nf = 0; nf < 4; nf++)
            #pragma unroll
            for (int q = 0; q < 4; q++) acc[mf][nf][q] = 0.0f;

    int nc = K >> 7;

    load_chunk8(A, HTOT, M, m0, E, K, V, n0, 0, a_base, b_base, tid);
    CP_COMMIT();

    int a_row_off = wm * 64 + ((lane >> 3) & 1) * 8 + (lane & 7);
    int a_col     = (lane >> 4) * 8;
    int b_row_off = wn * 32 + ((lane >> 4) & 1) * 8 + (lane & 7);
    int b_col     = ((lane >> 3) & 1) * 8;

    for (int c = 0; c < nc; c++) {
        if (c + 1 < nc) {
            load_chunk8(A, HTOT, M, m0, E, K, V, n0, (c + 1) << 7,
                        a_base + ((c + 1) & 1) * STAGE8, b_base + ((c + 1) & 1) * STAGE8, tid);
            CP_COMMIT();
            CP_WAIT1();
        } else {
            CP_WAIT0();
        }
        __syncthreads();
        uint32_t abase_s = a_base + (c & 1) * STAGE8;
        uint32_t bbase_s = b_base + (c & 1) * STAGE8;
        #pragma unroll
        for (int ks = 0; ks < 4; ks++) {
            uint32_t af[4][4], bf[2][4];
            #pragma unroll
            for (int mf = 0; mf < 4; mf++)
                ldsm_x4(af[mf], abase_s + ((a_row_off + mf * 16) * RST8U + a_col + ks * 16) * 2);
            #pragma unroll
            for (int p = 0; p < 2; p++)
                ldsm_x4(bf[p], bbase_s + ((b_row_off + p * 16) * RST8U + b_col + ks * 16) * 2);
            #pragma unroll
            for (int mf = 0; mf < 4; mf++)
                #pragma unroll
                for (int nf = 0; nf < 4; nf++)
                    mma_e4m3(acc[mf][nf], af[mf], &bf[nf >> 1][(nf & 1) * 2]);
        }
    }

    __syncthreads();
    #pragma unroll
    for (int mf = 0; mf < 4; mf++) {
        #pragma unroll
        for (int h = 0; h < 2; h++) {
            int rowb = wm * 64 + mf * 16 + h * 8 + gr;
            float sloc = 0.f, slloc = 0.f;
            #pragma unroll
            for (int nf = 0; nf < 4; nf++) {
                #pragma unroll
                for (int q = 0; q < 2; q++) {
                    int colb = wn * 32 + nf * 8 + gc * 2 + q;
                    if (n0 + colb < V) {
                        float z = acc[mf][nf][h * 2 + q] * EINV + s_bias[colb];
                        sloc += __expf(z);
                        slloc += z;
                    }
                }
            }
            sloc  += __shfl_xor_sync(0xffffffffu, sloc, 1);
            sloc  += __shfl_xor_sync(0xffffffffu, sloc, 2);
            slloc += __shfl_xor_sync(0xffffffffu, slloc, 1);
            slloc += __shfl_xor_sync(0xffffffffu, slloc, 2);
            if (gc == 0) {
                s_s[wn * 128 + rowb] = sloc;
                s_l[wn * 128 + rowb] = slloc;
            }
        }
    }
    __syncthreads();
    if (tid < 128) {
        int grow = m0 + tid;
        if (grow < M) {
            float s = s_s[tid] + s_s[128 + tid] + s_s[256 + tid] + s_s[384 + tid];
            float sl = s_l[tid] + s_l[128 + tid] + s_l[256 + tid] + s_l[384 + tid];
            atomicAdd(&g_se[head * MAXT + grow], s);
            atomicAdd(&g_sl[head * MAXT + grow], sl);
        }
    }
}

// ---------------- per-block BCE body (fp32 SIMT, 64x64 tiles) ----------------
__device__ void bce_block(int nIdx, int mIdx,
                          const float* __restrict__ emb, const float* __restrict__ vbias,
                          const float* __restrict__ aprob, const int* __restrict__ tsel,
                          const int* __restrict__ asel, int M, int V, int K, int hoff) {
    extern __shared__ __align__(16) char dyn[];
    float (*As)[68] = (float(*)[68])dyn;
    float (*Bs)[68] = (float(*)[68])(dyn + 16 * 68 * 4);
    float* red = (float*)(dyn + 2 * 16 * 68 * 4);
    int m0 = mIdx * 64, n0 = nIdx * 64;
    int tid = threadIdx.x;
    int tx = tid & 15, ty = tid >> 4;
    int lrow = tid >> 2, lk4 = (tid & 3) * 4;
    float acc[4][4] = {};
    for (int k0 = 0; k0 < K; k0 += 16) {
        float4 av = make_float4(0.f, 0.f, 0.f, 0.f);
        int ar = m0 + lrow;
        if (ar < M) {
            int pr = asel[ar];
            av = *(const float4*)(g_H + (size_t)pr * HTOT + hoff + k0 + lk4);
        }
        As[lk4 + 0][lrow] = av.x; As[lk4 + 1][lrow] = av.y;
        As[lk4 + 2][lrow] = av.z; As[lk4 + 3][lrow] = av.w;
        float4 bv = make_float4(0.f, 0.f, 0.f, 0.f);
        int br = n0 + lrow;
        if (br < V) bv = *(const float4*)(emb + (size_t)br * K + k0 + lk4);
        Bs[lk4 + 0][lrow] = bv.x; Bs[lk4 + 1][lrow] = bv.y;
        Bs[lk4 + 2][lrow] = bv.z; Bs[lk4 + 3][lrow] = bv.w;
        __syncthreads();
        #pragma unroll
        for (int k = 0; k < 16; k++) {
            float4 a4 = *(const float4*)&As[k][ty * 4];
            float4 b4 = *(const float4*)&Bs[k][tx * 4];
            float a_[4] = {a4.x, a4.y, a4.z, a4.w};
            float b_[4] = {b4.x, b4.y, b4.z, b4.w};
            #pragma unroll
            for (int r = 0; r < 4; r++)
                #pragma unroll
                for (int c = 0; c < 4; c++) acc[r][c] += a_[r] * b_[c];
        }
        __syncthreads();
    }
    float lsum = 0.f;
    #pragma unroll
    for (int r = 0; r < 4; r++) {
        int grow = m0 + ty * 4 + r;
        if (grow < M) {
            int trow = tsel[asel[grow]];
            #pragma unroll
            for (int c = 0; c < 4; c++) {
                int v = n0 + tx * 4 + c;
                if (v < V) {
                    float z = acc[r][c] + vbias[v];
                    float t = aprob[(size_t)trow * 360 + v];
                    lsum += fmaxf(z, 0.f) - z * t + log1pf(__expf(-fabsf(z)));
                }
            }
        }
    }
    red[tid] = lsum; __syncthreads();
    for (int o = 128; o > 0; o >>= 1) { if (tid < o) red[tid] += red[tid + o]; __syncthreads(); }
    if (tid == 0) atomicAdd(&g_acc[6], red[0]);
}

// ---------------- MEGA kernel: BCE + pos/morph/stem stats in ONE launch -------------------
__global__ void __launch_bounds__(256, 2)
mega_heads_k(const float* __restrict__ stem_bias, const float* __restrict__ pos_bias,
             const float* __restrict__ morph_bias,
             const float* __restrict__ aff_emb, const float* __restrict__ aff_bias,
             const float* __restrict__ aprob, const int* __restrict__ tsel,
             const int* __restrict__ asel,
             int T, int Ta, int mT, int mTa, int nvb_s) {
    int b = blockIdx.x;
    int nbb = 6 * mTa;
    if (b < nbb) {
        bce_block(b % 6, b / 6, aff_emb, aff_bias, aprob, tsel, asel, Ta, 360, 128, 512);
        return;
    }
    b -= nbb;
    if (b < 2 * mT) {
        stats_block(b % 2, b / 2, g_H8 + 256, g_E8p, pos_bias, T, 200, 128, 1);
        return;
    }
    b -= 2 * mT;
    if (b < 4 * mT) {
        stats_block(b % 4, b / 4, g_H8 + 384, g_E8m, morph_bias, T, 400, 128, 2);
        return;
    }
    b -= 4 * mT;
    stats_block(b % nvb_s, b / nvb_s, g_H8, g_E8, stem_bias, T, 50000, 256, 0);
}

// ---------------- merged reduce: all 3 softmax heads, 3T blocks ---------------------------
__global__ void reduce_all_k(const float* __restrict__ stem_emb, const float* __restrict__ pos_emb,
                             const float* __restrict__ morph_emb,
                             const float* __restrict__ stem_bias, const float* __restrict__ pos_bias,
                             const float* __restrict__ morph_bias,
                             const int* __restrict__ stems, const int* __restrict__ postags,
                             const int* __restrict__ morphs,
                             const int* __restrict__ tsel, int T) {
    int bx = blockIdx.x;
    int head = bx / T, row = bx - head * T;
    const float* emb; const float* vbias; const int* labels;
    int V, K, hoff, accoff;
    if (head == 0) { emb = stem_emb;  vbias = stem_bias;  labels = stems;   V = 50000; K = 256; hoff = 0;   accoff = 0; }
    else if (head == 1) { emb = pos_emb; vbias = pos_bias; labels = postags; V = 200; K = 128; hoff = 256; accoff = 2; }
    else { emb = morph_emb; vbias = morph_bias; labels = morphs; V = 400; K = 128; hoff = 384; accoff = 4; }

    int tid = threadIdx.x;   // 128 threads
    __shared__ float sd[128];
    int tgt = labels[tsel[row]];
    float d = 0.f;
    for (int k = tid; k < K; k += 128)
        d += g_H[(size_t)row * HTOT + hoff + k] * emb[(size_t)tgt * K + k];
    sd[tid] = d; __syncthreads();
    for (int o = 64; o > 0; o >>= 1) { if (tid < o) sd[tid] += sd[tid + o]; __syncthreads(); }
    if (tid == 0) {
        float logZ = logf(g_se[head * MAXT + row]);
        float tlogit = sd[0] + vbias[tgt];
        float nll = logZ - tlogit;
        float smooth = (float)V * logZ - g_sl[head * MAXT + row];
        atomicAdd(&g_acc[accoff], nll);
        atomicAdd(&g_acc[accoff + 1], smooth);
    }
}

// ---------------- finalize: assemble the 7 output scalars ----------------
__global__ void finalize_k(float* __restrict__ out, int T, int Ta) {
    if (threadIdx.x != 0 || blockIdx.x != 0) return;
    const int Vs[3] = {50000, 200, 400};
    for (int h = 0; h < 3; h++) {
        float nll_m = g_acc[2 * h] / (float)T;
        float sm_m  = g_acc[2 * h + 1] / (float)T;
        float eps_i = 0.1f / (float)(Vs[h] - 1);
        out[h] = (1.0f - 0.1f - eps_i) * nll_m + eps_i * sm_m;
        out[4 + h] = nll_m;
    }
    out[3] = g_acc[6] / ((float)Ta * 360.0f);
}

// ---------------- launch ----------------
extern "C" void kernel_launch(void* const* d_in, const int* in_sizes, int n_in,
                              void* d_out, int out_size) {
    const float* hid    = (const float*)d_in[0];
    const float* aprob  = (const float*)d_in[1];
    const int* stems    = (const int*)d_in[2];
    const int* postags  = (const int*)d_in[3];
    const int* morphs   = (const int*)d_in[4];
    const int* hsel     = (const int*)d_in[5];
    const int* tsel     = (const int*)d_in[6];
    const int* asel     = (const int*)d_in[7];
    const float* stem_emb  = (const float*)d_in[8];
    const float* stem_W    = (const float*)d_in[9];
    const float* stem_b    = (const float*)d_in[10];
    const float* stem_g    = (const float*)d_in[11];
    const float* stem_beta = (const float*)d_in[12];
    const float* stem_bias = (const float*)d_in[13];
    const float* pos_emb   = (const float*)d_in[14];
    const float* pos_W     = (const float*)d_in[15];
    const float* pos_b     = (const float*)d_in[16];
    const float* pos_g     = (const float*)d_in[17];
    const float* pos_beta  = (const float*)d_in[18];
    const float* pos_bias  = (const float*)d_in[19];
    const float* morph_emb = (const float*)d_in[20];
    const float* morph_W   = (const float*)d_in[21];
    const float* morph_b   = (const float*)d_in[22];
    const float* morph_g   = (const float*)d_in[23];
    const float* morph_beta= (const float*)d_in[24];
    const float* morph_bias= (const float*)d_in[25];
    const float* aff_emb   = (const float*)d_in[26];
    const float* aff_W     = (const float*)d_in[27];
    const float* aff_b     = (const float*)d_in[28];
    const float* aff_g     = (const float*)d_in[29];
    const float* aff_beta  = (const float*)d_in[30];
    const float* aff_bias  = (const float*)d_in[31];
    float* out = (float*)d_out;

    int T  = in_sizes[5];
    int Ta = in_sizes[7];
    int mT128 = (T + 127) / 128;
    int mTa = (Ta + 63) / 64;
    const int nvb_s = (50000 + 127) / 128;   // 391

    uint8_t* dE8;
    cudaGetSymbolAddress((void**)&dE8, g_E8);

    cudaFuncSetAttribute(mega_heads_k,
                         cudaFuncAttributeMaxDynamicSharedMemorySize, SMEM_STATS8);

    gather_x_k<<<T, 192>>>(hid, hsel);
    cvt_w_all_k<<<(HTOT * DMODEL + 255) / 256, 256>>>(stem_W, stem_b, pos_W, pos_b,
                                                      morph_W, morph_b, aff_W, aff_b);
    {
        const int nchunks = 50000 * 256 / 8 + 200 * 128 / 8 + 400 * 128 / 8;
        cvt_e8_all_k<<<(nchunks + 255) / 256, 256>>>(stem_emb, pos_emb, morph_emb);
    }

    gemm_tc_gelu<<<dim3(HTOT / 128, mT128), 256>>>(T);
    ln_all_k<<<(4 * T + 7) / 8, 256>>>(stem_g, stem_beta, pos_g, pos_beta,
                                       morph_g, morph_beta, aff_g, aff_beta, T);

    // single mega launch: BCE + pos + morph + stem stats
    {
        int nblocks = 6 * mTa + 2 * mT128 + 4 * mT128 + nvb_s * mT128;
        mega_heads_k<<<nblocks, 256, SMEM_STATS8>>>(stem_bias, pos_bias, morph_bias,
                                                    aff_emb, aff_bias, aprob, tsel, asel,
                                                    T, Ta, mT128, mTa, nvb_s);
    }

    reduce_all_k<<<3 * T, 128>>>(stem_emb, pos_emb, morph_emb,
                                 stem_bias, pos_bias, morph_bias,
                                 stems, postags, morphs, tsel, T);

    finalize_k<<<1, 32>>>(out, T, Ta);
}